// round 15
// baseline (speedup 1.0000x reference)
#include <cuda_runtime.h>
#include <cuda_bf16.h>
#include <stdint.h>
#include <math.h>

// ---------------- problem constants ----------------
#define B_    2
#define S_    512
#define M_    1024
#define D_    768
#define H_    12
#define DK_   64
#define DF_   3072
#define L_    12
#define V_    50257
#define QKVN  (3 * D_)     // 2304
#define EPS_  1e-5f

// ---------------- scratch (device globals) ----------------
__device__ float          g_x[M_ * D_];
__device__ __nv_bfloat16  g_h_hi[M_ * D_],  g_h_lo[M_ * D_];
__device__ __nv_bfloat16  g_q_hi[M_ * D_],  g_q_lo[M_ * D_];
__device__ __nv_bfloat16  g_k_hi[M_ * D_],  g_k_lo[M_ * D_];
__device__ __nv_bfloat16  g_v_hi[M_ * D_],  g_v_lo[M_ * D_];
__device__ __nv_bfloat16  g_att_hi[M_ * D_], g_att_lo[M_ * D_];
__device__ __nv_bfloat16  g_ff_hi[M_ * DF_], g_ff_lo[M_ * DF_];
__device__ __nv_bfloat16  g_wqkv_hi[L_ * QKVN * D_], g_wqkv_lo[L_ * QKVN * D_];
__device__ __nv_bfloat16  g_wo_hi[L_ * D_ * D_],     g_wo_lo[L_ * D_ * D_];
__device__ __nv_bfloat16  g_w1_hi[L_ * DF_ * D_],    g_w1_lo[L_ * DF_ * D_];
__device__ __nv_bfloat16  g_w2_hi[L_ * D_ * DF_],    g_w2_lo[L_ * D_ * DF_];
__device__ __nv_bfloat16  g_tok_hi[(size_t)V_ * D_], g_tok_lo[(size_t)V_ * D_];
__device__ float          g_bqkv[L_ * QKVN];

// ---------------- small helpers ----------------
__device__ __forceinline__ void split_bf16(float x, __nv_bfloat16& hi, __nv_bfloat16& lo) {
    hi = __float2bfloat16(x);
    lo = __float2bfloat16(x - __bfloat162float(hi));
}

__device__ __forceinline__ uint32_t pack2(float lo, float hi) {
    __nv_bfloat162 t = __floats2bfloat162_rn(lo, hi);
    return *(uint32_t*)&t;
}

__device__ __forceinline__ uint32_t packbf(__nv_bfloat16 lo, __nv_bfloat16 hi) {
    return ((uint32_t)*(uint16_t*)&hi << 16) | (uint32_t)*(uint16_t*)&lo;
}

__device__ __forceinline__ void cp16(uint32_t saddr, const void* g) {
    asm volatile("cp.async.cg.shared.global [%0], [%1], 16;\n" :: "r"(saddr), "l"(g));
}
#define CP_COMMIT() asm volatile("cp.async.commit_group;\n" ::: "memory")

__device__ __forceinline__ void ldm4(uint32_t a[4], uint32_t saddr) {
    asm volatile("ldmatrix.sync.aligned.m8n8.x4.shared.b16 {%0,%1,%2,%3}, [%4];"
                 : "=r"(a[0]), "=r"(a[1]), "=r"(a[2]), "=r"(a[3]) : "r"(saddr));
}

__device__ __forceinline__ void mma_bf16(float c[4], const uint32_t a[4], const uint32_t b[2]) {
    asm volatile("mma.sync.aligned.m16n8k16.row.col.f32.bf16.bf16.f32 "
                 "{%0,%1,%2,%3}, {%4,%5,%6,%7}, {%8,%9}, {%0,%1,%2,%3};"
                 : "+f"(c[0]), "+f"(c[1]), "+f"(c[2]), "+f"(c[3])
                 : "r"(a[0]), "r"(a[1]), "r"(a[2]), "r"(a[3]),
                   "r"(b[0]), "r"(b[1]));
}

// ---------------- prepass ----------------
__global__ void splitT_kernel(const float* __restrict__ src,
                              __nv_bfloat16* __restrict__ dhi,
                              __nv_bfloat16* __restrict__ dlo,
                              int K, int N,
                              size_t srcLayer, size_t dstLayer,
                              int dstRowOff, int dstLd) {
    __shared__ float t[32][33];
    int n0 = blockIdx.x * 32, k0 = blockIdx.y * 32, l = blockIdx.z;
    const float* s = src + (size_t)l * srcLayer;
    int c = threadIdx.x & 31, r8 = threadIdx.x >> 5;
    #pragma unroll
    for (int i = 0; i < 4; i++) {
        int r = r8 + i * 8;
        t[r][c] = s[(size_t)(k0 + r) * N + n0 + c];
    }
    __syncthreads();
    int c2 = threadIdx.x & 15, rr = threadIdx.x >> 4;
    #pragma unroll
    for (int i = 0; i < 2; i++) {
        int nloc = rr + i * 16;
        float x0 = t[2 * c2][nloc];
        float x1 = t[2 * c2 + 1][nloc];
        __nv_bfloat16 h0, l0, h1, l1;
        split_bf16(x0, h0, l0);
        split_bf16(x1, h1, l1);
        size_t o = (size_t)l * dstLayer + (size_t)(dstRowOff + n0 + nloc) * dstLd + k0 + 2 * c2;
        *(uint32_t*)&dhi[o] = packbf(h0, h1);
        *(uint32_t*)&dlo[o] = packbf(l0, l1);
    }
}

__global__ void split_kernel(const float* __restrict__ src,
                             __nv_bfloat16* __restrict__ dhi,
                             __nv_bfloat16* __restrict__ dlo, size_t n4) {
    const float4* s4 = (const float4*)src;
    uint2* dh = (uint2*)dhi;
    uint2* dl = (uint2*)dlo;
    size_t stride = (size_t)gridDim.x * blockDim.x;
    for (size_t i = (size_t)blockIdx.x * blockDim.x + threadIdx.x; i < n4; i += stride) {
        float4 v = s4[i];
        __nv_bfloat16 h0, l0, h1, l1, h2, l2, h3, l3;
        split_bf16(v.x, h0, l0);
        split_bf16(v.y, h1, l1);
        split_bf16(v.z, h2, l2);
        split_bf16(v.w, h3, l3);
        uint2 oh, ol;
        oh.x = packbf(h0, h1); oh.y = packbf(h2, h3);
        ol.x = packbf(l0, l1); ol.y = packbf(l2, l3);
        dh[i] = oh;
        dl[i] = ol;
    }
}

__global__ void bconcat_kernel(const float* __restrict__ bq,
                               const float* __restrict__ bk,
                               const float* __restrict__ bv,
                               float* __restrict__ o) {
    int l = blockIdx.y;
    int i = blockIdx.x * 256 + threadIdx.x;
    if (i < D_) {
        o[l * QKVN + i]           = bq[l * D_ + i];
        o[l * QKVN + D_ + i]      = bk[l * D_ + i];
        o[l * QKVN + 2 * D_ + i]  = bv[l * D_ + i];
    }
}

// ---------------- embedding ----------------
__global__ void embed_kernel(const int* __restrict__ ids,
                             const float* __restrict__ tok,
                             const float* __restrict__ pos,
                             float* __restrict__ x) {
    int r = blockIdx.x;
    int s = r % S_;
    int id = ids[r];
    const float* t = tok + (size_t)id * D_;
    const float* p = pos + (size_t)s  * D_;
    float* xr = x + (size_t)r * D_;
    for (int d = threadIdx.x; d < D_; d += blockDim.x)
        xr[d] = t[d] + p[d];
}

// ---------------- single-pass layernorm (warp-shuffle reduction) ----------------
__global__ void ln_kernel(const float* __restrict__ x,
                          const float* __restrict__ g,
                          const float* __restrict__ b,
                          __nv_bfloat16* __restrict__ yhi,
                          __nv_bfloat16* __restrict__ ylo) {
    __shared__ float w1s[8], w2s[8], stats[2];
    int r = blockIdx.x;
    int tid = threadIdx.x;
    int lane = tid & 31, warp = tid >> 5;
    const float* xr = x + (size_t)r * D_;

    float vals[3];
    float s1 = 0.f, s2 = 0.f;
    #pragma unroll
    for (int i = 0; i < 3; i++) {
        float v = xr[tid + i * 256];
        vals[i] = v;
        s1 += v;
        s2 += v * v;
    }
    #pragma unroll
    for (int o = 16; o > 0; o >>= 1) {
        s1 += __shfl_xor_sync(0xffffffff, s1, o);
        s2 += __shfl_xor_sync(0xffffffff, s2, o);
    }
    if (lane == 0) { w1s[warp] = s1; w2s[warp] = s2; }
    __syncthreads();
    if (warp == 0) {
        float a1 = (lane < 8) ? w1s[lane] : 0.f;
        float a2 = (lane < 8) ? w2s[lane] : 0.f;
        #pragma unroll
        for (int o = 4; o > 0; o >>= 1) {
            a1 += __shfl_xor_sync(0xffffffff, a1, o);
            a2 += __shfl_xor_sync(0xffffffff, a2, o);
        }
        if (lane == 0) {
            float mean = a1 * (1.0f / D_);
            float var  = a2 * (1.0f / D_) - mean * mean;
            stats[0] = mean;
            stats[1] = rsqrtf(var + EPS_);
        }
    }
    __syncthreads();
    float mean = stats[0], inv = stats[1];

    #pragma unroll
    for (int i = 0; i < 3; i++) {
        int d = tid + i * 256;
        float y = (vals[i] - mean) * inv * g[d] + b[d];
        __nv_bfloat16 hi, lo; split_bf16(y, hi, lo);
        yhi[(size_t)r * D_ + d] = hi;
        ylo[(size_t)r * D_ + d] = lo;
    }
}

enum { EPI_NONE = 0, EPI_RESID = 1, EPI_GELU_SPLIT = 2, EPI_QKV = 3 };

// ---------------- bf16x3 GEMM: 128xBN tile, 3-stage cp.async pipeline ----------------
#define G_STAGE(BN_) (16384 + 2 * (BN_) * 80)
#define G_SMEM(BN_)  (3 * G_STAGE(BN_))

template<int EPI, int BN_>
__global__ __launch_bounds__(256, 2)
void bf16x3_gemm(const __nv_bfloat16* __restrict__ Ahi,
                 const __nv_bfloat16* __restrict__ Alo,
                 const __nv_bfloat16* __restrict__ Bhi,
                 const __nv_bfloat16* __restrict__ Blo,
                 const float* __restrict__ bias,
                 const float* __restrict__ resid,
                 float* __restrict__ C,
                 __nv_bfloat16* __restrict__ Chi,
                 __nv_bfloat16* __restrict__ Clo,
                 __nv_bfloat16* __restrict__ Xhi,
                 __nv_bfloat16* __restrict__ Xlo,
                 __nv_bfloat16* __restrict__ Yhi,
                 __nv_bfloat16* __restrict__ Ylo,
                 int M, int N, int K, int ldc) {
    constexpr int NT = (BN_ == 64) ? 4 : 2;
    constexpr int STAGE = G_STAGE(BN_);
    extern __shared__ __align__(16) char smem_raw[];
    uint32_t sbase = (uint32_t)__cvta_generic_to_shared(smem_raw);

    int tid  = threadIdx.x;
    int lane = tid & 31;
    int warp = tid >> 5;
    int gid  = lane >> 2;
    int tig  = lane & 3;
    int wm   = (warp >> 1) * 32;
    int wn   = (warp & 1) * (BN_ / 2);
    int m0   = blockIdx.y * 128;
    int n0   = blockIdx.x * BN_;

    float acc[2][NT][4];
    #pragma unroll
    for (int i = 0; i < 2; i++)
        #pragma unroll
        for (int j = 0; j < NT; j++)
            #pragma unroll
            for (int e = 0; e < 4; e++) acc[i][j][e] = 0.f;

    auto loadStage = [&](int kt, int st) {
        uint32_t s0 = sbase + st * STAGE;
        int k0 = kt * 32;
        #pragma unroll
        for (int i = 0; i < 2; i++) {
            int cid = tid + i * 256;
            int r = cid >> 2, c = cid & 3;
            uint32_t soff = (uint32_t)((r * 4 + (c ^ ((r >> 1) & 3))) * 16);
            size_t go = (size_t)(m0 + r) * K + k0 + c * 8;
            cp16(s0 + soff,        Ahi + go);
            cp16(s0 + 8192 + soff, Alo + go);
        }
        for (int cid = tid; cid < BN_ * 4; cid += 256) {
            int r = cid >> 2, c = cid & 3;
            int rr = n0 + r; if (rr > N - 1) rr = N - 1;
            uint32_t soff = (uint32_t)(r * 80 + c * 16);
            size_t go = (size_t)rr * K + k0 + c * 8;
            cp16(s0 + 16384 + soff,            Bhi + go);
            cp16(s0 + 16384 + BN_ * 80 + soff, Blo + go);
        }
    };

    const int nIt = K / 32;
    loadStage(0, 0); CP_COMMIT();
    loadStage(1, 1); CP_COMMIT();

    int grp    = lane >> 3;
    int bRowLo = (lane & 7);
    int bKoff  = (grp & 1) ? 16 : 0;

    for (int it = 0; it < nIt; ++it) {
        if (it + 1 < nIt) asm volatile("cp.async.wait_group 1;\n" ::: "memory");
        else              asm volatile("cp.async.wait_group 0;\n" ::: "memory");
        __syncthreads();
        if (it + 2 < nIt) {
            loadStage(it + 2, (it + 2) % 3);
            CP_COMMIT();
        }

        int st = it % 3;
        uint32_t sAhiB = sbase + st * STAGE;
        uint32_t sAloB = sAhiB + 8192;
        uint32_t sBhiA = sAhiB + 16384;
        uint32_t sBloA = sBhiA + BN_ * 80;

        #pragma unroll
        for (int ks = 0; ks < 2; ks++) {
            uint32_t bh[NT][2], bl[NT][2];
            #pragma unroll
            for (int np = 0; np < NT / 2; np++) {
                int nt0 = np * 2, nt1 = np * 2 + 1;
                int nrow = wn + ((grp < 2) ? nt0 : nt1) * 8 + bRowLo;
                uint32_t off = (uint32_t)(nrow * 80 + ks * 32 + bKoff);
                uint32_t r4[4];
                ldm4(r4, sBhiA + off);
                bh[nt0][0] = r4[0]; bh[nt0][1] = r4[1];
                bh[nt1][0] = r4[2]; bh[nt1][1] = r4[3];
                ldm4(r4, sBloA + off);
                bl[nt0][0] = r4[0]; bl[nt0][1] = r4[1];
                bl[nt1][0] = r4[2]; bl[nt1][1] = r4[3];
            }
            #pragma unroll
            for (int mt = 0; mt < 2; mt++) {
                int r = wm + mt * 16 + (lane & 15);
                int c = ks * 2 + (lane >> 4);
                uint32_t soff = (uint32_t)((r * 4 + (c ^ ((r >> 1) & 3))) * 16);
                uint32_t ah[4], al[4];
                ldm4(ah, sAhiB + soff);
                ldm4(al, sAloB + soff);
                #pragma unroll
                for (int nt = 0; nt < NT; nt++) {
                    mma_bf16(acc[mt][nt], ah, bh[nt]);
                    mma_bf16(acc[mt][nt], ah, bl[nt]);
                    mma_bf16(acc[mt][nt], al, bh[nt]);
                }
            }
        }
    }

    // ---- epilogue ----
    int seg = 0;
    __nv_bfloat16 *DsHi = Chi, *DsLo = Clo;
    float qscale = 1.0f;
    if (EPI == EPI_QKV) {
        seg = n0 / D_;
        if (seg == 1) { DsHi = Xhi; DsLo = Xlo; }
        if (seg == 2) { DsHi = Yhi; DsLo = Ylo; }
        if (seg == 0) qscale = 0.125f;
    }

    #pragma unroll
    for (int mt = 0; mt < 2; mt++) {
        #pragma unroll
        for (int nt = 0; nt < NT; nt++) {
            #pragma unroll
            for (int half = 0; half < 2; half++) {
                int gm = m0 + wm + mt * 16 + gid + half * 8;
                int gn0 = n0 + wn + nt * 8 + tig * 2;
                if (EPI == EPI_QKV || EPI == EPI_GELU_SPLIT) {
                    float cv0 = acc[mt][nt][half * 2 + 0];
                    float cv1 = acc[mt][nt][half * 2 + 1];
                    if (bias) { cv0 += bias[gn0]; cv1 += bias[gn0 + 1]; }
                    if (EPI == EPI_QKV) { cv0 *= qscale; cv1 *= qscale; }
                    if (EPI == EPI_GELU_SPLIT) {
                        cv0 = 0.5f * cv0 * (1.0f + erff(cv0 * 0.70710678118654752f));
                        cv1 = 0.5f * cv1 * (1.0f + erff(cv1 * 0.70710678118654752f));
                    }
                    __nv_bfloat16 h0, l0, h1, l1;
                    split_bf16(cv0, h0, l0);
                    split_bf16(cv1, h1, l1);
                    size_t o = (EPI == EPI_QKV)
                             ? ((size_t)gm * D_ + (gn0 - seg * D_))
                             : ((size_t)gm * ldc + gn0);
                    __nv_bfloat16* dh = (EPI == EPI_QKV) ? DsHi : Chi;
                    __nv_bfloat16* dl = (EPI == EPI_QKV) ? DsLo : Clo;
                    *(uint32_t*)&dh[o] = packbf(h0, h1);
                    *(uint32_t*)&dl[o] = packbf(l0, l1);
                } else {
                    #pragma unroll
                    for (int e = 0; e < 2; e++) {
                        int gn = gn0 + e;
                        if (gn >= N) continue;
                        float cv = acc[mt][nt][half * 2 + e];
                        if (bias) cv += bias[gn];
                        size_t o = (size_t)gm * ldc + gn;
                        if (EPI == EPI_RESID) cv += resid[o];
                        C[o] = cv;
                    }
                }
            }
        }
    }
}

// ---------------- tensor-core flash attention: 2 heads / block ----------------
// 256 threads = 2 warp-groups; group g handles head blockIdx.y*2+g with its own
// SMEM slice. Identical loop counts -> shared block barrier is safe.
#define APITCH 72
#define AGRP   (6 * 64 * APITCH)              // elems per head-group slice
#define ATTN_SMEM_BYTES (2 * AGRP * 2)        // 110,592 B

__global__ __launch_bounds__(256)
void attn_mma_kernel(const __nv_bfloat16* __restrict__ qhi,
                     const __nv_bfloat16* __restrict__ qlo,
                     const __nv_bfloat16* __restrict__ khi,
                     const __nv_bfloat16* __restrict__ klo,
                     const __nv_bfloat16* __restrict__ vhi,
                     const __nv_bfloat16* __restrict__ vlo,
                     __nv_bfloat16* __restrict__ ohi,
                     __nv_bfloat16* __restrict__ olo) {
    extern __shared__ __nv_bfloat16 sb[];
    int tid   = threadIdx.x;
    int grpid = tid >> 7;               // 0,1 -> head group
    int t128  = tid & 127;
    __nv_bfloat16* base = sb + grpid * AGRP;
    __nv_bfloat16* sQh = base;
    __nv_bfloat16* sQl = base + 1 * 64 * APITCH;
    __nv_bfloat16* sKh = base + 2 * 64 * APITCH;
    __nv_bfloat16* sKl = base + 3 * 64 * APITCH;
    __nv_bfloat16* sVh = base + 4 * 64 * APITCH;
    __nv_bfloat16* sVl = base + 5 * 64 * APITCH;
    uint32_t sQhA = (uint32_t)__cvta_generic_to_shared(sQh);
    uint32_t sQlA = (uint32_t)__cvta_generic_to_shared(sQl);
    uint32_t sKhA = (uint32_t)__cvta_generic_to_shared(sKh);
    uint32_t sKlA = (uint32_t)__cvta_generic_to_shared(sKl);

    int qt = 7 - blockIdx.x;
    int h  = blockIdx.y * 2 + grpid;
    int b  = blockIdx.z;
    int lane = tid & 31;
    int warp = (tid >> 5) & 3;          // warp within group
    int gid  = lane >> 2;
    int tig  = lane & 3;
    int q0 = qt * 64;
    int rowbase = warp * 16;

    #pragma unroll
    for (int i = 0; i < 4; i++) {
        int idx = t128 + i * 128;
        int r = idx >> 3, c = idx & 7;
        size_t go = (size_t)(b * S_ + q0 + r) * D_ + h * DK_ + c * 8;
        uint32_t soff = (uint32_t)(r * 144 + c * 16);
        cp16(sQhA + soff, qhi + go);
        cp16(sQlA + soff, qlo + go);
    }
    CP_COMMIT();

    float m0r = -1e30f, m1r = -1e30f;
    float l0r = 0.f,    l1r = 0.f;
    float oacc[8][4];
    #pragma unroll
    for (int i = 0; i < 8; i++)
        #pragma unroll
        for (int e = 0; e < 4; e++) oacc[i][e] = 0.f;

    for (int jt = 0; jt <= qt; jt++) {
        #pragma unroll
        for (int i = 0; i < 4; i++) {
            int idx = t128 + i * 128;
            int r = idx >> 3, c = idx & 7;
            size_t go = (size_t)(b * S_ + jt * 64 + r) * D_ + h * DK_ + c * 8;
            uint32_t soff = (uint32_t)(r * 144 + c * 16);
            cp16(sKhA + soff, khi + go);
            cp16(sKlA + soff, klo + go);
        }
        CP_COMMIT();
        uint16_t* sVh16 = (uint16_t*)sVh;
        uint16_t* sVl16 = (uint16_t*)sVl;
        #pragma unroll
        for (int i = 0; i < 16; i++) {
            int idx = t128 + i * 128;
            int j = idx >> 5, d = (idx & 31) * 2;
            size_t go = (size_t)(b * S_ + jt * 64 + j) * D_ + h * DK_ + d;
            uint32_t vh = *(const uint32_t*)&vhi[go];
            uint32_t vl = *(const uint32_t*)&vlo[go];
            sVh16[d * APITCH + j]       = (uint16_t)(vh & 0xffff);
            sVh16[(d + 1) * APITCH + j] = (uint16_t)(vh >> 16);
            sVl16[d * APITCH + j]       = (uint16_t)(vl & 0xffff);
            sVl16[(d + 1) * APITCH + j] = (uint16_t)(vl >> 16);
        }
        asm volatile("cp.async.wait_group 0;\n" ::: "memory");
        __syncthreads();

        float sc[8][4];
        #pragma unroll
        for (int i = 0; i < 8; i++)
            #pragma unroll
            for (int e = 0; e < 4; e++) sc[i][e] = 0.f;

        #pragma unroll
        for (int ks = 0; ks < 4; ks++) {
            int r0 = rowbase + gid, r1 = rowbase + gid + 8;
            int kc = ks * 16 + 2 * tig;
            uint32_t ah[4], al[4];
            ah[0] = *(uint32_t*)&sQh[r0 * APITCH + kc];
            ah[1] = *(uint32_t*)&sQh[r1 * APITCH + kc];
            ah[2] = *(uint32_t*)&sQh[r0 * APITCH + kc + 8];
            ah[3] = *(uint32_t*)&sQh[r1 * APITCH + kc + 8];
            al[0] = *(uint32_t*)&sQl[r0 * APITCH + kc];
            al[1] = *(uint32_t*)&sQl[r1 * APITCH + kc];
            al[2] = *(uint32_t*)&sQl[r0 * APITCH + kc + 8];
            al[3] = *(uint32_t*)&sQl[r1 * APITCH + kc + 8];
            #pragma unroll
            for (int nf = 0; nf < 8; nf++) {
                int n = nf * 8 + gid;
                uint32_t bh[2], bl[2];
                bh[0] = *(uint32_t*)&sKh[n * APITCH + kc];
                bh[1] = *(uint32_t*)&sKh[n * APITCH + kc + 8];
                bl[0] = *(uint32_t*)&sKl[n * APITCH + kc];
                bl[1] = *(uint32_t*)&sKl[n * APITCH + kc + 8];
                mma_bf16(sc[nf], ah, bh);
                mma_bf16(sc[nf], ah, bl);
                mma_bf16(sc[nf], al, bh);
            }
        }

        if (jt == qt) {
            int ql0 = rowbase + gid, ql1 = ql0 + 8;
            #pragma unroll
            for (int nf = 0; nf < 8; nf++) {
                int j0 = nf * 8 + 2 * tig;
                if (j0     > ql0) sc[nf][0] = -1e30f;
                if (j0 + 1 > ql0) sc[nf][1] = -1e30f;
                if (j0     > ql1) sc[nf][2] = -1e30f;
                if (j0 + 1 > ql1) sc[nf][3] = -1e30f;
            }
        }

        float mx0 = -1e30f, mx1 = -1e30f;
        #pragma unroll
        for (int nf = 0; nf < 8; nf++) {
            mx0 = fmaxf(mx0, fmaxf(sc[nf][0], sc[nf][1]));
            mx1 = fmaxf(mx1, fmaxf(sc[nf][2], sc[nf][3]));
        }
        mx0 = fmaxf(mx0, __shfl_xor_sync(0xffffffff, mx0, 1));
        mx0 = fmaxf(mx0, __shfl_xor_sync(0xffffffff, mx0, 2));
        mx1 = fmaxf(mx1, __shfl_xor_sync(0xffffffff, mx1, 1));
        mx1 = fmaxf(mx1, __shfl_xor_sync(0xffffffff, mx1, 2));

        float mn0 = fmaxf(m0r, mx0), mn1 = fmaxf(m1r, mx1);
        float al0 = __expf(m0r - mn0), al1 = __expf(m1r - mn1);
        m0r = mn0; m1r = mn1;

        float sum0 = 0.f, sum1 = 0.f;
        #pragma unroll
        for (int nf = 0; nf < 8; nf++) {
            sc[nf][0] = __expf(sc[nf][0] - mn0);
            sc[nf][1] = __expf(sc[nf][1] - mn0);
            sc[nf][2] = __expf(sc[nf][2] - mn1);
            sc[nf][3] = __expf(sc[nf][3] - mn1);
            sum0 += sc[nf][0] + sc[nf][1];
            sum1 += sc[nf][2] + sc[nf][3];
        }
        sum0 += __shfl_xor_sync(0xffffffff, sum0, 1);
        sum0 += __shfl_xor_sync(0xffffffff, sum0, 2);
        sum1 += __shfl_xor_sync(0xffffffff, sum1, 1);
        sum1 += __shfl_xor_sync(0xffffffff, sum1, 2);
        l0r = l0r * al0 + sum0;
        l1r = l1r * al1 + sum1;

        #pragma unroll
        for (int df = 0; df < 8; df++) {
            oacc[df][0] *= al0; oacc[df][1] *= al0;
            oacc[df][2] *= al1; oacc[df][3] *= al1;
        }

        #pragma unroll
        for (int ks = 0; ks < 4; ks++) {
            int f0 = 2 * ks, f1 = 2 * ks + 1;
            float h00 = __bfloat162float(__float2bfloat16(sc[f0][0]));
            float h01 = __bfloat162float(__float2bfloat16(sc[f0][1]));
            float h02 = __bfloat162float(__float2bfloat16(sc[f0][2]));
            float h03 = __bfloat162float(__float2bfloat16(sc[f0][3]));
            float h10 = __bfloat162float(__float2bfloat16(sc[f1][0]));
            float h11 = __bfloat162float(__float2bfloat16(sc[f1][1]));
            float h12 = __bfloat162float(__float2bfloat16(sc[f1][2]));
            float h13 = __bfloat162float(__float2bfloat16(sc[f1][3]));
            uint32_t ph[4], pl[4];
            ph[0] = pack2(h00, h01);
            ph[1] = pack2(h02, h03);
            ph[2] = pack2(h10, h11);
            ph[3] = pack2(h12, h13);
            pl[0] = pack2(sc[f0][0] - h00, sc[f0][1] - h01);
            pl[1] = pack2(sc[f0][2] - h02, sc[f0][3] - h03);
            pl[2] = pack2(sc[f1][0] - h10, sc[f1][1] - h11);
            pl[3] = pack2(sc[f1][2] - h12, sc[f1][3] - h13);

            int kc = ks * 16 + 2 * tig;
            #pragma unroll
            for (int df = 0; df < 8; df++) {
                int d = df * 8 + gid;
                uint32_t bh[2], bl[2];
                bh[0] = *(uint32_t*)&sVh[d * APITCH + kc];
                bh[1] = *(uint32_t*)&sVh[d * APITCH + kc + 8];
                bl[0] = *(uint32_t*)&sVl[d * APITCH + kc];
                bl[1] = *(uint32_t*)&sVl[d * APITCH + kc + 8];
                mma_bf16(oacc[df], ph, bh);
                mma_bf16(oacc[df], ph, bl);
                mma_bf16(oacc[df], pl, bh);
            }
        }
        __syncthreads();
    }

    float inv0 = 1.0f / l0r, inv1 = 1.0f / l1r;
    int r0 = b * S_ + q0 + rowbase + gid;
    int r1 = r0 + 8;
    #pragma unroll
    for (int df = 0; df < 8; df++) {
        int d = h * DK_ + df * 8 + 2 * tig;
        float o0 = oacc[df][0] * inv0, o1 = oacc[df][1] * inv0;
        float o2 = oacc[df][2] * inv1, o3 = oacc[df][3] * inv1;
        __nv_bfloat16 hi0, lo0, hi1, lo1;
        split_bf16(o0, hi0, lo0); split_bf16(o1, hi1, lo1);
        *(uint32_t*)&ohi[(size_t)r0 * D_ + d] = packbf(hi0, hi1);
        *(uint32_t*)&olo[(size_t)r0 * D_ + d] = packbf(lo0, lo1);
        split_bf16(o2, hi0, lo0); split_bf16(o3, hi1, lo1);
        *(uint32_t*)&ohi[(size_t)r1 * D_ + d] = packbf(hi0, hi1);
        *(uint32_t*)&olo[(size_t)r1 * D_ + d] = packbf(lo0, lo1);
    }
}

// ---------------- host orchestration ----------------
extern "C" void kernel_launch(void* const* d_in, const int* in_sizes, int n_in,
                              void* d_out, int out_size) {
    const int*   ids   = (const int*)  d_in[0];
    const float* tok   = (const float*)d_in[1];
    const float* pos   = (const float*)d_in[2];
    const float* wq    = (const float*)d_in[3];
    const float* bq    = (const float*)d_in[4];
    const float* wk    = (const float*)d_in[5];
    const float* bk    = (const float*)d_in[6];
    const float* wv    = (const float*)d_in[7];
    const float* bv    = (const float*)d_in[8];
    const float* wo    = (const float*)d_in[9];
    const float* bo    = (const float*)d_in[10];
    const float* w1    = (const float*)d_in[11];
    const float* b1    = (const float*)d_in[12];
    const float* w2    = (const float*)d_in[13];
    const float* b2    = (const float*)d_in[14];
    const float* ln1g  = (const float*)d_in[15];
    const float* ln1b  = (const float*)d_in[16];
    const float* ln2g  = (const float*)d_in[17];
    const float* ln2b  = (const float*)d_in[18];
    const float* lnfg  = (const float*)d_in[19];
    const float* lnfb  = (const float*)d_in[20];
    float* out = (float*)d_out;

    float *x, *bqkv;
    __nv_bfloat16 *hhi, *hlo, *qhi, *qlo, *khi, *klo, *vhi, *vlo;
    __nv_bfloat16 *atthi, *attlo, *ffhi, *fflo;
    __nv_bfloat16 *wqkvhi, *wqkvlo, *wohi, *wolo, *w1hi, *w1lo, *w2hi, *w2lo, *tokhi, *toklo;
    cudaGetSymbolAddress((void**)&x,      g_x);
    cudaGetSymbolAddress((void**)&bqkv,   g_bqkv);
    cudaGetSymbolAddress((void**)&hhi,    g_h_hi);
    cudaGetSymbolAddress((void**)&hlo,    g_h_lo);
    cudaGetSymbolAddress((void**)&qhi,    g_q_hi);
    cudaGetSymbolAddress((void**)&qlo,    g_q_lo);
    cudaGetSymbolAddress((void**)&khi,    g_k_hi);
    cudaGetSymbolAddress((void**)&klo,    g_k_lo);
    cudaGetSymbolAddress((void**)&vhi,    g_v_hi);
    cudaGetSymbolAddress((void**)&vlo,    g_v_lo);
    cudaGetSymbolAddress((void**)&atthi,  g_att_hi);
    cudaGetSymbolAddress((void**)&attlo,  g_att_lo);
    cudaGetSymbolAddress((void**)&ffhi,   g_ff_hi);
    cudaGetSymbolAddress((void**)&fflo,   g_ff_lo);
    cudaGetSymbolAddress((void**)&wqkvhi, g_wqkv_hi);
    cudaGetSymbolAddress((void**)&wqkvlo, g_wqkv_lo);
    cudaGetSymbolAddress((void**)&wohi,   g_wo_hi);
    cudaGetSymbolAddress((void**)&wolo,   g_wo_lo);
    cudaGetSymbolAddress((void**)&w1hi,   g_w1_hi);
    cudaGetSymbolAddress((void**)&w1lo,   g_w1_lo);
    cudaGetSymbolAddress((void**)&w2hi,   g_w2_hi);
    cudaGetSymbolAddress((void**)&w2lo,   g_w2_lo);
    cudaGetSymbolAddress((void**)&tokhi,  g_tok_hi);
    cudaGetSymbolAddress((void**)&toklo,  g_tok_lo);

    const int smem64 = G_SMEM(64);
    const int smem32 = G_SMEM(32);
    cudaFuncSetAttribute(bf16x3_gemm<EPI_NONE, 64>,
                         cudaFuncAttributeMaxDynamicSharedMemorySize, smem64);
    cudaFuncSetAttribute(bf16x3_gemm<EPI_QKV, 64>,
                         cudaFuncAttributeMaxDynamicSharedMemorySize, smem64);
    cudaFuncSetAttribute(bf16x3_gemm<EPI_GELU_SPLIT, 64>,
                         cudaFuncAttributeMaxDynamicSharedMemorySize, smem64);
    cudaFuncSetAttribute(bf16x3_gemm<EPI_RESID, 32>,
                         cudaFuncAttributeMaxDynamicSharedMemorySize, smem32);
    cudaFuncSetAttribute(attn_mma_kernel,
                         cudaFuncAttributeMaxDynamicSharedMemorySize, ATTN_SMEM_BYTES);

    // ---- prepass ----
    splitT_kernel<<<dim3(D_/32, D_/32, L_), 256>>>(
        wq, wqkvhi, wqkvlo, D_, D_, (size_t)D_*D_, (size_t)QKVN*D_, 0,     D_);
    splitT_kernel<<<dim3(D_/32, D_/32, L_), 256>>>(
        wk, wqkvhi, wqkvlo, D_, D_, (size_t)D_*D_, (size_t)QKVN*D_, D_,    D_);
    splitT_kernel<<<dim3(D_/32, D_/32, L_), 256>>>(
        wv, wqkvhi, wqkvlo, D_, D_, (size_t)D_*D_, (size_t)QKVN*D_, 2*D_,  D_);
    splitT_kernel<<<dim3(D_/32, D_/32, L_), 256>>>(
        wo, wohi, wolo, D_, D_, (size_t)D_*D_, (size_t)D_*D_, 0, D_);
    splitT_kernel<<<dim3(DF_/32, D_/32, L_), 256>>>(
        w1, w1hi, w1lo, D_, DF_, (size_t)D_*DF_, (size_t)DF_*D_, 0, D_);
    splitT_kernel<<<dim3(D_/32, DF_/32, L_), 256>>>(
        w2, w2hi, w2lo, DF_, D_, (size_t)DF_*D_, (size_t)D_*DF_, 0, DF_);
    split_kernel<<<2048, 256>>>(tok, tokhi, toklo, ((size_t)V_ * D_) / 4);
    bconcat_kernel<<<dim3(3, L_), 256>>>(bq, bk, bv, bqkv);

    embed_kernel<<<M_, 256>>>(ids, tok, pos, x);

    for (int l = 0; l < L_; l++) {
        ln_kernel<<<M_, 256>>>(x, ln1g + l * D_, ln1b + l * D_, hhi, hlo);

        bf16x3_gemm<EPI_QKV, 64><<<dim3(QKVN/64, M_/128), 256, smem64>>>(
            hhi, hlo,
            wqkvhi + (size_t)l * QKVN * D_, wqkvlo + (size_t)l * QKVN * D_,
            bqkv + l * QKVN, nullptr, nullptr,
            qhi, qlo, khi, klo, vhi, vlo,
            M_, QKVN, D_, QKVN);

        attn_mma_kernel<<<dim3(8, H_/2, B_), 256, ATTN_SMEM_BYTES>>>(
            qhi, qlo, khi, klo, vhi, vlo, atthi, attlo);

        bf16x3_gemm<EPI_RESID, 32><<<dim3(D_/32, M_/128), 256, smem32>>>(
            atthi, attlo,
            wohi + (size_t)l * D_ * D_, wolo + (size_t)l * D_ * D_,
            bo + l * D_, x, x, nullptr, nullptr, nullptr, nullptr, nullptr, nullptr,
            M_, D_, D_, D_);

        ln_kernel<<<M_, 256>>>(x, ln2g + l * D_, ln2b + l * D_, hhi, hlo);

        bf16x3_gemm<EPI_GELU_SPLIT, 64><<<dim3(DF_/64, M_/128), 256, smem64>>>(
            hhi, hlo,
            w1hi + (size_t)l * DF_ * D_, w1lo + (size_t)l * DF_ * D_,
            b1 + l * DF_, nullptr, nullptr, ffhi, fflo, nullptr, nullptr, nullptr, nullptr,
            M_, DF_, D_, DF_);

        bf16x3_gemm<EPI_RESID, 32><<<dim3(D_/32, M_/128), 256, smem32>>>(
            ffhi, fflo,
            w2hi + (size_t)l * D_ * DF_, w2lo + (size_t)l * D_ * DF_,
            b2 + l * D_, x, x, nullptr, nullptr, nullptr, nullptr, nullptr, nullptr,
            M_, D_, DF_, D_);
    }

    ln_kernel<<<M_, 256>>>(x, lnfg, lnfb, hhi, hlo);

    bf16x3_gemm<EPI_NONE, 64><<<dim3((V_ + 63) / 64, M_/128), 256, smem64>>>(
        hhi, hlo, tokhi, toklo,
        nullptr, nullptr, out, nullptr, nullptr, nullptr, nullptr, nullptr, nullptr,
        M_, V_, D_, V_);
}

// round 16
// speedup vs baseline: 1.0515x; 1.0515x over previous
#include <cuda_runtime.h>
#include <cuda_bf16.h>
#include <stdint.h>
#include <math.h>

// ---------------- problem constants ----------------
#define B_    2
#define S_    512
#define M_    1024
#define D_    768
#define H_    12
#define DK_   64
#define DF_   3072
#define L_    12
#define V_    50257
#define QKVN  (3 * D_)     // 2304
#define EPS_  1e-5f

// ---------------- scratch (device globals) ----------------
__device__ float          g_x[M_ * D_];
__device__ __nv_bfloat16  g_h_hi[M_ * D_],  g_h_lo[M_ * D_];
__device__ __nv_bfloat16  g_q_hi[M_ * D_],  g_q_lo[M_ * D_];
__device__ __nv_bfloat16  g_k_hi[M_ * D_],  g_k_lo[M_ * D_];
__device__ __nv_bfloat16  g_v_hi[M_ * D_],  g_v_lo[M_ * D_];
__device__ __nv_bfloat16  g_att_hi[M_ * D_], g_att_lo[M_ * D_];
__device__ __nv_bfloat16  g_ff_hi[M_ * DF_], g_ff_lo[M_ * DF_];
__device__ __nv_bfloat16  g_wqkv_hi[L_ * QKVN * D_], g_wqkv_lo[L_ * QKVN * D_];
__device__ __nv_bfloat16  g_wo_hi[L_ * D_ * D_],     g_wo_lo[L_ * D_ * D_];
__device__ __nv_bfloat16  g_w1_hi[L_ * DF_ * D_],    g_w1_lo[L_ * DF_ * D_];
__device__ __nv_bfloat16  g_w2_hi[L_ * D_ * DF_],    g_w2_lo[L_ * D_ * DF_];
__device__ __nv_bfloat16  g_tok_hi[(size_t)V_ * D_], g_tok_lo[(size_t)V_ * D_];
__device__ float          g_bqkv[L_ * QKVN];

// ---------------- small helpers ----------------
__device__ __forceinline__ void split_bf16(float x, __nv_bfloat16& hi, __nv_bfloat16& lo) {
    hi = __float2bfloat16(x);
    lo = __float2bfloat16(x - __bfloat162float(hi));
}

__device__ __forceinline__ uint32_t pack2(float lo, float hi) {
    __nv_bfloat162 t = __floats2bfloat162_rn(lo, hi);
    return *(uint32_t*)&t;
}

__device__ __forceinline__ uint32_t packbf(__nv_bfloat16 lo, __nv_bfloat16 hi) {
    return ((uint32_t)*(uint16_t*)&hi << 16) | (uint32_t)*(uint16_t*)&lo;
}

__device__ __forceinline__ void cp16(uint32_t saddr, const void* g) {
    asm volatile("cp.async.cg.shared.global [%0], [%1], 16;\n" :: "r"(saddr), "l"(g));
}
#define CP_COMMIT() asm volatile("cp.async.commit_group;\n" ::: "memory")

__device__ __forceinline__ void ldm4(uint32_t a[4], uint32_t saddr) {
    asm volatile("ldmatrix.sync.aligned.m8n8.x4.shared.b16 {%0,%1,%2,%3}, [%4];"
                 : "=r"(a[0]), "=r"(a[1]), "=r"(a[2]), "=r"(a[3]) : "r"(saddr));
}

__device__ __forceinline__ void ldm4t(uint32_t a[4], uint32_t saddr) {
    asm volatile("ldmatrix.sync.aligned.m8n8.x4.trans.shared.b16 {%0,%1,%2,%3}, [%4];"
                 : "=r"(a[0]), "=r"(a[1]), "=r"(a[2]), "=r"(a[3]) : "r"(saddr));
}

__device__ __forceinline__ void mma_bf16(float c[4], const uint32_t a[4], const uint32_t b[2]) {
    asm volatile("mma.sync.aligned.m16n8k16.row.col.f32.bf16.bf16.f32 "
                 "{%0,%1,%2,%3}, {%4,%5,%6,%7}, {%8,%9}, {%0,%1,%2,%3};"
                 : "+f"(c[0]), "+f"(c[1]), "+f"(c[2]), "+f"(c[3])
                 : "r"(a[0]), "r"(a[1]), "r"(a[2]), "r"(a[3]),
                   "r"(b[0]), "r"(b[1]));
}

// ---------------- prepass ----------------
__global__ void splitT_kernel(const float* __restrict__ src,
                              __nv_bfloat16* __restrict__ dhi,
                              __nv_bfloat16* __restrict__ dlo,
                              int K, int N,
                              size_t srcLayer, size_t dstLayer,
                              int dstRowOff, int dstLd) {
    __shared__ float t[32][33];
    int n0 = blockIdx.x * 32, k0 = blockIdx.y * 32, l = blockIdx.z;
    const float* s = src + (size_t)l * srcLayer;
    int c = threadIdx.x & 31, r8 = threadIdx.x >> 5;
    #pragma unroll
    for (int i = 0; i < 4; i++) {
        int r = r8 + i * 8;
        t[r][c] = s[(size_t)(k0 + r) * N + n0 + c];
    }
    __syncthreads();
    int c2 = threadIdx.x & 15, rr = threadIdx.x >> 4;
    #pragma unroll
    for (int i = 0; i < 2; i++) {
        int nloc = rr + i * 16;
        float x0 = t[2 * c2][nloc];
        float x1 = t[2 * c2 + 1][nloc];
        __nv_bfloat16 h0, l0, h1, l1;
        split_bf16(x0, h0, l0);
        split_bf16(x1, h1, l1);
        size_t o = (size_t)l * dstLayer + (size_t)(dstRowOff + n0 + nloc) * dstLd + k0 + 2 * c2;
        *(uint32_t*)&dhi[o] = packbf(h0, h1);
        *(uint32_t*)&dlo[o] = packbf(l0, l1);
    }
}

__global__ void split_kernel(const float* __restrict__ src,
                             __nv_bfloat16* __restrict__ dhi,
                             __nv_bfloat16* __restrict__ dlo, size_t n4) {
    const float4* s4 = (const float4*)src;
    uint2* dh = (uint2*)dhi;
    uint2* dl = (uint2*)dlo;
    size_t stride = (size_t)gridDim.x * blockDim.x;
    for (size_t i = (size_t)blockIdx.x * blockDim.x + threadIdx.x; i < n4; i += stride) {
        float4 v = s4[i];
        __nv_bfloat16 h0, l0, h1, l1, h2, l2, h3, l3;
        split_bf16(v.x, h0, l0);
        split_bf16(v.y, h1, l1);
        split_bf16(v.z, h2, l2);
        split_bf16(v.w, h3, l3);
        uint2 oh, ol;
        oh.x = packbf(h0, h1); oh.y = packbf(h2, h3);
        ol.x = packbf(l0, l1); ol.y = packbf(l2, l3);
        dh[i] = oh;
        dl[i] = ol;
    }
}

__global__ void bconcat_kernel(const float* __restrict__ bq,
                               const float* __restrict__ bk,
                               const float* __restrict__ bv,
                               float* __restrict__ o) {
    int l = blockIdx.y;
    int i = blockIdx.x * 256 + threadIdx.x;
    if (i < D_) {
        o[l * QKVN + i]           = bq[l * D_ + i];
        o[l * QKVN + D_ + i]      = bk[l * D_ + i];
        o[l * QKVN + 2 * D_ + i]  = bv[l * D_ + i];
    }
}

// ---------------- embedding ----------------
__global__ void embed_kernel(const int* __restrict__ ids,
                             const float* __restrict__ tok,
                             const float* __restrict__ pos,
                             float* __restrict__ x) {
    int r = blockIdx.x;
    int s = r % S_;
    int id = ids[r];
    const float* t = tok + (size_t)id * D_;
    const float* p = pos + (size_t)s  * D_;
    float* xr = x + (size_t)r * D_;
    for (int d = threadIdx.x; d < D_; d += blockDim.x)
        xr[d] = t[d] + p[d];
}

// ---------------- single-pass layernorm (warp-shuffle reduction) ----------------
__global__ void ln_kernel(const float* __restrict__ x,
                          const float* __restrict__ g,
                          const float* __restrict__ b,
                          __nv_bfloat16* __restrict__ yhi,
                          __nv_bfloat16* __restrict__ ylo) {
    __shared__ float w1s[8], w2s[8], stats[2];
    int r = blockIdx.x;
    int tid = threadIdx.x;
    int lane = tid & 31, warp = tid >> 5;
    const float* xr = x + (size_t)r * D_;

    float vals[3];
    float s1 = 0.f, s2 = 0.f;
    #pragma unroll
    for (int i = 0; i < 3; i++) {
        float v = xr[tid + i * 256];
        vals[i] = v;
        s1 += v;
        s2 += v * v;
    }
    #pragma unroll
    for (int o = 16; o > 0; o >>= 1) {
        s1 += __shfl_xor_sync(0xffffffff, s1, o);
        s2 += __shfl_xor_sync(0xffffffff, s2, o);
    }
    if (lane == 0) { w1s[warp] = s1; w2s[warp] = s2; }
    __syncthreads();
    if (warp == 0) {
        float a1 = (lane < 8) ? w1s[lane] : 0.f;
        float a2 = (lane < 8) ? w2s[lane] : 0.f;
        #pragma unroll
        for (int o = 4; o > 0; o >>= 1) {
            a1 += __shfl_xor_sync(0xffffffff, a1, o);
            a2 += __shfl_xor_sync(0xffffffff, a2, o);
        }
        if (lane == 0) {
            float mean = a1 * (1.0f / D_);
            float var  = a2 * (1.0f / D_) - mean * mean;
            stats[0] = mean;
            stats[1] = rsqrtf(var + EPS_);
        }
    }
    __syncthreads();
    float mean = stats[0], inv = stats[1];

    #pragma unroll
    for (int i = 0; i < 3; i++) {
        int d = tid + i * 256;
        float y = (vals[i] - mean) * inv * g[d] + b[d];
        __nv_bfloat16 hi, lo; split_bf16(y, hi, lo);
        yhi[(size_t)r * D_ + d] = hi;
        ylo[(size_t)r * D_ + d] = lo;
    }
}

enum { EPI_NONE = 0, EPI_RESID = 1, EPI_GELU_SPLIT = 2, EPI_QKV = 3 };

// ---------------- bf16x3 GEMM: 128xBN tile, 3-stage cp.async pipeline ----------------
#define G_STAGE(BN_) (16384 + 2 * (BN_) * 80)
#define G_SMEM(BN_)  (3 * G_STAGE(BN_))

template<int EPI, int BN_>
__global__ __launch_bounds__(256, 2)
void bf16x3_gemm(const __nv_bfloat16* __restrict__ Ahi,
                 const __nv_bfloat16* __restrict__ Alo,
                 const __nv_bfloat16* __restrict__ Bhi,
                 const __nv_bfloat16* __restrict__ Blo,
                 const float* __restrict__ bias,
                 const float* __restrict__ resid,
                 float* __restrict__ C,
                 __nv_bfloat16* __restrict__ Chi,
                 __nv_bfloat16* __restrict__ Clo,
                 __nv_bfloat16* __restrict__ Xhi,
                 __nv_bfloat16* __restrict__ Xlo,
                 __nv_bfloat16* __restrict__ Yhi,
                 __nv_bfloat16* __restrict__ Ylo,
                 int M, int N, int K, int ldc) {
    constexpr int NT = (BN_ == 64) ? 4 : 2;
    constexpr int STAGE = G_STAGE(BN_);
    extern __shared__ __align__(16) char smem_raw[];
    uint32_t sbase = (uint32_t)__cvta_generic_to_shared(smem_raw);

    int tid  = threadIdx.x;
    int lane = tid & 31;
    int warp = tid >> 5;
    int gid  = lane >> 2;
    int tig  = lane & 3;
    int wm   = (warp >> 1) * 32;
    int wn   = (warp & 1) * (BN_ / 2);
    int m0   = blockIdx.y * 128;
    int n0   = blockIdx.x * BN_;

    float acc[2][NT][4];
    #pragma unroll
    for (int i = 0; i < 2; i++)
        #pragma unroll
        for (int j = 0; j < NT; j++)
            #pragma unroll
            for (int e = 0; e < 4; e++) acc[i][j][e] = 0.f;

    auto loadStage = [&](int kt, int st) {
        uint32_t s0 = sbase + st * STAGE;
        int k0 = kt * 32;
        #pragma unroll
        for (int i = 0; i < 2; i++) {
            int cid = tid + i * 256;
            int r = cid >> 2, c = cid & 3;
            uint32_t soff = (uint32_t)((r * 4 + (c ^ ((r >> 1) & 3))) * 16);
            size_t go = (size_t)(m0 + r) * K + k0 + c * 8;
            cp16(s0 + soff,        Ahi + go);
            cp16(s0 + 8192 + soff, Alo + go);
        }
        for (int cid = tid; cid < BN_ * 4; cid += 256) {
            int r = cid >> 2, c = cid & 3;
            int rr = n0 + r; if (rr > N - 1) rr = N - 1;
            uint32_t soff = (uint32_t)(r * 80 + c * 16);
            size_t go = (size_t)rr * K + k0 + c * 8;
            cp16(s0 + 16384 + soff,            Bhi + go);
            cp16(s0 + 16384 + BN_ * 80 + soff, Blo + go);
        }
    };

    const int nIt = K / 32;
    loadStage(0, 0); CP_COMMIT();
    loadStage(1, 1); CP_COMMIT();

    int grp    = lane >> 3;
    int bRowLo = (lane & 7);
    int bKoff  = (grp & 1) ? 16 : 0;

    for (int it = 0; it < nIt; ++it) {
        if (it + 1 < nIt) asm volatile("cp.async.wait_group 1;\n" ::: "memory");
        else              asm volatile("cp.async.wait_group 0;\n" ::: "memory");
        __syncthreads();
        if (it + 2 < nIt) {
            loadStage(it + 2, (it + 2) % 3);
            CP_COMMIT();
        }

        int st = it % 3;
        uint32_t sAhiB = sbase + st * STAGE;
        uint32_t sAloB = sAhiB + 8192;
        uint32_t sBhiA = sAhiB + 16384;
        uint32_t sBloA = sBhiA + BN_ * 80;

        #pragma unroll
        for (int ks = 0; ks < 2; ks++) {
            uint32_t bh[NT][2], bl[NT][2];
            #pragma unroll
            for (int np = 0; np < NT / 2; np++) {
                int nt0 = np * 2, nt1 = np * 2 + 1;
                int nrow = wn + ((grp < 2) ? nt0 : nt1) * 8 + bRowLo;
                uint32_t off = (uint32_t)(nrow * 80 + ks * 32 + bKoff);
                uint32_t r4[4];
                ldm4(r4, sBhiA + off);
                bh[nt0][0] = r4[0]; bh[nt0][1] = r4[1];
                bh[nt1][0] = r4[2]; bh[nt1][1] = r4[3];
                ldm4(r4, sBloA + off);
                bl[nt0][0] = r4[0]; bl[nt0][1] = r4[1];
                bl[nt1][0] = r4[2]; bl[nt1][1] = r4[3];
            }
            #pragma unroll
            for (int mt = 0; mt < 2; mt++) {
                int r = wm + mt * 16 + (lane & 15);
                int c = ks * 2 + (lane >> 4);
                uint32_t soff = (uint32_t)((r * 4 + (c ^ ((r >> 1) & 3))) * 16);
                uint32_t ah[4], al[4];
                ldm4(ah, sAhiB + soff);
                ldm4(al, sAloB + soff);
                #pragma unroll
                for (int nt = 0; nt < NT; nt++) {
                    mma_bf16(acc[mt][nt], ah, bh[nt]);
                    mma_bf16(acc[mt][nt], ah, bl[nt]);
                    mma_bf16(acc[mt][nt], al, bh[nt]);
                }
            }
        }
    }

    // ---- epilogue ----
    int seg = 0;
    __nv_bfloat16 *DsHi = Chi, *DsLo = Clo;
    float qscale = 1.0f;
    if (EPI == EPI_QKV) {
        seg = n0 / D_;
        if (seg == 1) { DsHi = Xhi; DsLo = Xlo; }
        if (seg == 2) { DsHi = Yhi; DsLo = Ylo; }
        if (seg == 0) qscale = 0.125f;
    }

    #pragma unroll
    for (int mt = 0; mt < 2; mt++) {
        #pragma unroll
        for (int nt = 0; nt < NT; nt++) {
            #pragma unroll
            for (int half = 0; half < 2; half++) {
                int gm = m0 + wm + mt * 16 + gid + half * 8;
                int gn0 = n0 + wn + nt * 8 + tig * 2;
                if (EPI == EPI_QKV || EPI == EPI_GELU_SPLIT) {
                    float cv0 = acc[mt][nt][half * 2 + 0];
                    float cv1 = acc[mt][nt][half * 2 + 1];
                    if (bias) { cv0 += bias[gn0]; cv1 += bias[gn0 + 1]; }
                    if (EPI == EPI_QKV) { cv0 *= qscale; cv1 *= qscale; }
                    if (EPI == EPI_GELU_SPLIT) {
                        cv0 = 0.5f * cv0 * (1.0f + erff(cv0 * 0.70710678118654752f));
                        cv1 = 0.5f * cv1 * (1.0f + erff(cv1 * 0.70710678118654752f));
                    }
                    __nv_bfloat16 h0, l0, h1, l1;
                    split_bf16(cv0, h0, l0);
                    split_bf16(cv1, h1, l1);
                    size_t o = (EPI == EPI_QKV)
                             ? ((size_t)gm * D_ + (gn0 - seg * D_))
                             : ((size_t)gm * ldc + gn0);
                    __nv_bfloat16* dh = (EPI == EPI_QKV) ? DsHi : Chi;
                    __nv_bfloat16* dl = (EPI == EPI_QKV) ? DsLo : Clo;
                    *(uint32_t*)&dh[o] = packbf(h0, h1);
                    *(uint32_t*)&dl[o] = packbf(l0, l1);
                } else {
                    #pragma unroll
                    for (int e = 0; e < 2; e++) {
                        int gn = gn0 + e;
                        if (gn >= N) continue;
                        float cv = acc[mt][nt][half * 2 + e];
                        if (bias) cv += bias[gn];
                        size_t o = (size_t)gm * ldc + gn;
                        if (EPI == EPI_RESID) cv += resid[o];
                        C[o] = cv;
                    }
                }
            }
        }
    }
}

// ---------------- tensor-core flash attention (V via ldmatrix.trans) ----------------
// All of Q,K,V stored [row][d] with pitch 72 (144 B, 16B-aligned for cp.async).
#define APITCH 72
#define ATTN_SMEM_BYTES (6 * 64 * APITCH * 2)

__global__ __launch_bounds__(128)
void attn_mma_kernel(const __nv_bfloat16* __restrict__ qhi,
                     const __nv_bfloat16* __restrict__ qlo,
                     const __nv_bfloat16* __restrict__ khi,
                     const __nv_bfloat16* __restrict__ klo,
                     const __nv_bfloat16* __restrict__ vhi,
                     const __nv_bfloat16* __restrict__ vlo,
                     __nv_bfloat16* __restrict__ ohi,
                     __nv_bfloat16* __restrict__ olo) {
    extern __shared__ __nv_bfloat16 sb[];
    __nv_bfloat16* sQh = sb;
    __nv_bfloat16* sQl = sb + 1 * 64 * APITCH;
    __nv_bfloat16* sKh = sb + 2 * 64 * APITCH;
    __nv_bfloat16* sKl = sb + 3 * 64 * APITCH;
    __nv_bfloat16* sVh = sb + 4 * 64 * APITCH;   // [j][d], NOT transposed
    __nv_bfloat16* sVl = sb + 5 * 64 * APITCH;
    uint32_t sQhA = (uint32_t)__cvta_generic_to_shared(sQh);
    uint32_t sQlA = (uint32_t)__cvta_generic_to_shared(sQl);
    uint32_t sKhA = (uint32_t)__cvta_generic_to_shared(sKh);
    uint32_t sKlA = (uint32_t)__cvta_generic_to_shared(sKl);
    uint32_t sVhA = (uint32_t)__cvta_generic_to_shared(sVh);
    uint32_t sVlA = (uint32_t)__cvta_generic_to_shared(sVl);

    int qt = 7 - blockIdx.x;
    int h  = blockIdx.y;
    int b  = blockIdx.z;
    int tid  = threadIdx.x;
    int lane = tid & 31;
    int warp = tid >> 5;
    int gid  = lane >> 2;
    int tig  = lane & 3;
    int q0 = qt * 64;
    int rowbase = warp * 16;

    #pragma unroll
    for (int i = 0; i < 4; i++) {
        int idx = tid + i * 128;
        int r = idx >> 3, c = idx & 7;
        size_t go = (size_t)(b * S_ + q0 + r) * D_ + h * DK_ + c * 8;
        uint32_t soff = (uint32_t)(r * 144 + c * 16);
        cp16(sQhA + soff, qhi + go);
        cp16(sQlA + soff, qlo + go);
    }
    CP_COMMIT();

    float m0r = -1e30f, m1r = -1e30f;
    float l0r = 0.f,    l1r = 0.f;
    float oacc[8][4];
    #pragma unroll
    for (int i = 0; i < 8; i++)
        #pragma unroll
        for (int e = 0; e < 4; e++) oacc[i][e] = 0.f;

    for (int jt = 0; jt <= qt; jt++) {
        // K and V: identical cp.async row loads
        #pragma unroll
        for (int i = 0; i < 4; i++) {
            int idx = tid + i * 128;
            int r = idx >> 3, c = idx & 7;
            size_t go = (size_t)(b * S_ + jt * 64 + r) * D_ + h * DK_ + c * 8;
            uint32_t soff = (uint32_t)(r * 144 + c * 16);
            cp16(sKhA + soff, khi + go);
            cp16(sKlA + soff, klo + go);
            cp16(sVhA + soff, vhi + go);
            cp16(sVlA + soff, vlo + go);
        }
        CP_COMMIT();
        asm volatile("cp.async.wait_group 0;\n" ::: "memory");
        __syncthreads();

        float sc[8][4];
        #pragma unroll
        for (int i = 0; i < 8; i++)
            #pragma unroll
            for (int e = 0; e < 4; e++) sc[i][e] = 0.f;

        #pragma unroll
        for (int ks = 0; ks < 4; ks++) {
            int r0 = rowbase + gid, r1 = rowbase + gid + 8;
            int kc = ks * 16 + 2 * tig;
            uint32_t ah[4], al[4];
            ah[0] = *(uint32_t*)&sQh[r0 * APITCH + kc];
            ah[1] = *(uint32_t*)&sQh[r1 * APITCH + kc];
            ah[2] = *(uint32_t*)&sQh[r0 * APITCH + kc + 8];
            ah[3] = *(uint32_t*)&sQh[r1 * APITCH + kc + 8];
            al[0] = *(uint32_t*)&sQl[r0 * APITCH + kc];
            al[1] = *(uint32_t*)&sQl[r1 * APITCH + kc];
            al[2] = *(uint32_t*)&sQl[r0 * APITCH + kc + 8];
            al[3] = *(uint32_t*)&sQl[r1 * APITCH + kc + 8];
            #pragma unroll
            for (int nf = 0; nf < 8; nf++) {
                int n = nf * 8 + gid;
                uint32_t bh[2], bl[2];
                bh[0] = *(uint32_t*)&sKh[n * APITCH + kc];
                bh[1] = *(uint32_t*)&sKh[n * APITCH + kc + 8];
                bl[0] = *(uint32_t*)&sKl[n * APITCH + kc];
                bl[1] = *(uint32_t*)&sKl[n * APITCH + kc + 8];
                mma_bf16(sc[nf], ah, bh);
                mma_bf16(sc[nf], ah, bl);
                mma_bf16(sc[nf], al, bh);
            }
        }

        if (jt == qt) {
            int ql0 = rowbase + gid, ql1 = ql0 + 8;
            #pragma unroll
            for (int nf = 0; nf < 8; nf++) {
                int j0 = nf * 8 + 2 * tig;
                if (j0     > ql0) sc[nf][0] = -1e30f;
                if (j0 + 1 > ql0) sc[nf][1] = -1e30f;
                if (j0     > ql1) sc[nf][2] = -1e30f;
                if (j0 + 1 > ql1) sc[nf][3] = -1e30f;
            }
        }

        float mx0 = -1e30f, mx1 = -1e30f;
        #pragma unroll
        for (int nf = 0; nf < 8; nf++) {
            mx0 = fmaxf(mx0, fmaxf(sc[nf][0], sc[nf][1]));
            mx1 = fmaxf(mx1, fmaxf(sc[nf][2], sc[nf][3]));
        }
        mx0 = fmaxf(mx0, __shfl_xor_sync(0xffffffff, mx0, 1));
        mx0 = fmaxf(mx0, __shfl_xor_sync(0xffffffff, mx0, 2));
        mx1 = fmaxf(mx1, __shfl_xor_sync(0xffffffff, mx1, 1));
        mx1 = fmaxf(mx1, __shfl_xor_sync(0xffffffff, mx1, 2));

        float mn0 = fmaxf(m0r, mx0), mn1 = fmaxf(m1r, mx1);
        float al0 = __expf(m0r - mn0), al1 = __expf(m1r - mn1);
        m0r = mn0; m1r = mn1;

        float sum0 = 0.f, sum1 = 0.f;
        #pragma unroll
        for (int nf = 0; nf < 8; nf++) {
            sc[nf][0] = __expf(sc[nf][0] - mn0);
            sc[nf][1] = __expf(sc[nf][1] - mn0);
            sc[nf][2] = __expf(sc[nf][2] - mn1);
            sc[nf][3] = __expf(sc[nf][3] - mn1);
            sum0 += sc[nf][0] + sc[nf][1];
            sum1 += sc[nf][2] + sc[nf][3];
        }
        sum0 += __shfl_xor_sync(0xffffffff, sum0, 1);
        sum0 += __shfl_xor_sync(0xffffffff, sum0, 2);
        sum1 += __shfl_xor_sync(0xffffffff, sum1, 1);
        sum1 += __shfl_xor_sync(0xffffffff, sum1, 2);
        l0r = l0r * al0 + sum0;
        l1r = l1r * al1 + sum1;

        #pragma unroll
        for (int df = 0; df < 8; df++) {
            oacc[df][0] *= al0; oacc[df][1] *= al0;
            oacc[df][2] *= al1; oacc[df][3] *= al1;
        }

        // P @ V with ldmatrix.trans B-fragments from [j][d] layout.
        // trans-x4: lanes 0-15 rows ks*16+(lane&15) at col dp*16+(lane>>4)*8.
        int vrow = (lane & 15);
        int vcolsel = (lane >> 4) * 8;
        #pragma unroll
        for (int ks = 0; ks < 4; ks++) {
            int f0 = 2 * ks, f1 = 2 * ks + 1;
            float h00 = __bfloat162float(__float2bfloat16(sc[f0][0]));
            float h01 = __bfloat162float(__float2bfloat16(sc[f0][1]));
            float h02 = __bfloat162float(__float2bfloat16(sc[f0][2]));
            float h03 = __bfloat162float(__float2bfloat16(sc[f0][3]));
            float h10 = __bfloat162float(__float2bfloat16(sc[f1][0]));
            float h11 = __bfloat162float(__float2bfloat16(sc[f1][1]));
            float h12 = __bfloat162float(__float2bfloat16(sc[f1][2]));
            float h13 = __bfloat162float(__float2bfloat16(sc[f1][3]));
            uint32_t ph[4], pl[4];
            ph[0] = pack2(h00, h01);
            ph[1] = pack2(h02, h03);
            ph[2] = pack2(h10, h11);
            ph[3] = pack2(h12, h13);
            pl[0] = pack2(sc[f0][0] - h00, sc[f0][1] - h01);
            pl[1] = pack2(sc[f0][2] - h02, sc[f0][3] - h03);
            pl[2] = pack2(sc[f1][0] - h10, sc[f1][1] - h11);
            pl[3] = pack2(sc[f1][2] - h12, sc[f1][3] - h13);

            uint32_t rowoff = (uint32_t)((ks * 16 + vrow) * 144);
            #pragma unroll
            for (int dp = 0; dp < 4; dp++) {
                uint32_t off = rowoff + (uint32_t)((dp * 16 + vcolsel) * 2);
                uint32_t r4h[4], r4l[4];
                ldm4t(r4h, sVhA + off);
                ldm4t(r4l, sVlA + off);
                uint32_t bh0[2] = { r4h[0], r4h[1] };
                uint32_t bh1[2] = { r4h[2], r4h[3] };
                uint32_t bl0[2] = { r4l[0], r4l[1] };
                uint32_t bl1[2] = { r4l[2], r4l[3] };
                mma_bf16(oacc[dp * 2],     ph, bh0);
                mma_bf16(oacc[dp * 2],     ph, bl0);
                mma_bf16(oacc[dp * 2],     pl, bh0);
                mma_bf16(oacc[dp * 2 + 1], ph, bh1);
                mma_bf16(oacc[dp * 2 + 1], ph, bl1);
                mma_bf16(oacc[dp * 2 + 1], pl, bh1);
            }
        }
        __syncthreads();
    }

    float inv0 = 1.0f / l0r, inv1 = 1.0f / l1r;
    int r0 = b * S_ + q0 + rowbase + gid;
    int r1 = r0 + 8;
    #pragma unroll
    for (int df = 0; df < 8; df++) {
        int d = h * DK_ + df * 8 + 2 * tig;
        float o0 = oacc[df][0] * inv0, o1 = oacc[df][1] * inv0;
        float o2 = oacc[df][2] * inv1, o3 = oacc[df][3] * inv1;
        __nv_bfloat16 hi0, lo0, hi1, lo1;
        split_bf16(o0, hi0, lo0); split_bf16(o1, hi1, lo1);
        *(uint32_t*)&ohi[(size_t)r0 * D_ + d] = packbf(hi0, hi1);
        *(uint32_t*)&olo[(size_t)r0 * D_ + d] = packbf(lo0, lo1);
        split_bf16(o2, hi0, lo0); split_bf16(o3, hi1, lo1);
        *(uint32_t*)&ohi[(size_t)r1 * D_ + d] = packbf(hi0, hi1);
        *(uint32_t*)&olo[(size_t)r1 * D_ + d] = packbf(lo0, lo1);
    }
}

// ---------------- host orchestration ----------------
extern "C" void kernel_launch(void* const* d_in, const int* in_sizes, int n_in,
                              void* d_out, int out_size) {
    const int*   ids   = (const int*)  d_in[0];
    const float* tok   = (const float*)d_in[1];
    const float* pos   = (const float*)d_in[2];
    const float* wq    = (const float*)d_in[3];
    const float* bq    = (const float*)d_in[4];
    const float* wk    = (const float*)d_in[5];
    const float* bk    = (const float*)d_in[6];
    const float* wv    = (const float*)d_in[7];
    const float* bv    = (const float*)d_in[8];
    const float* wo    = (const float*)d_in[9];
    const float* bo    = (const float*)d_in[10];
    const float* w1    = (const float*)d_in[11];
    const float* b1    = (const float*)d_in[12];
    const float* w2    = (const float*)d_in[13];
    const float* b2    = (const float*)d_in[14];
    const float* ln1g  = (const float*)d_in[15];
    const float* ln1b  = (const float*)d_in[16];
    const float* ln2g  = (const float*)d_in[17];
    const float* ln2b  = (const float*)d_in[18];
    const float* lnfg  = (const float*)d_in[19];
    const float* lnfb  = (const float*)d_in[20];
    float* out = (float*)d_out;

    float *x, *bqkv;
    __nv_bfloat16 *hhi, *hlo, *qhi, *qlo, *khi, *klo, *vhi, *vlo;
    __nv_bfloat16 *atthi, *attlo, *ffhi, *fflo;
    __nv_bfloat16 *wqkvhi, *wqkvlo, *wohi, *wolo, *w1hi, *w1lo, *w2hi, *w2lo, *tokhi, *toklo;
    cudaGetSymbolAddress((void**)&x,      g_x);
    cudaGetSymbolAddress((void**)&bqkv,   g_bqkv);
    cudaGetSymbolAddress((void**)&hhi,    g_h_hi);
    cudaGetSymbolAddress((void**)&hlo,    g_h_lo);
    cudaGetSymbolAddress((void**)&qhi,    g_q_hi);
    cudaGetSymbolAddress((void**)&qlo,    g_q_lo);
    cudaGetSymbolAddress((void**)&khi,    g_k_hi);
    cudaGetSymbolAddress((void**)&klo,    g_k_lo);
    cudaGetSymbolAddress((void**)&vhi,    g_v_hi);
    cudaGetSymbolAddress((void**)&vlo,    g_v_lo);
    cudaGetSymbolAddress((void**)&atthi,  g_att_hi);
    cudaGetSymbolAddress((void**)&attlo,  g_att_lo);
    cudaGetSymbolAddress((void**)&ffhi,   g_ff_hi);
    cudaGetSymbolAddress((void**)&fflo,   g_ff_lo);
    cudaGetSymbolAddress((void**)&wqkvhi, g_wqkv_hi);
    cudaGetSymbolAddress((void**)&wqkvlo, g_wqkv_lo);
    cudaGetSymbolAddress((void**)&wohi,   g_wo_hi);
    cudaGetSymbolAddress((void**)&wolo,   g_wo_lo);
    cudaGetSymbolAddress((void**)&w1hi,   g_w1_hi);
    cudaGetSymbolAddress((void**)&w1lo,   g_w1_lo);
    cudaGetSymbolAddress((void**)&w2hi,   g_w2_hi);
    cudaGetSymbolAddress((void**)&w2lo,   g_w2_lo);
    cudaGetSymbolAddress((void**)&tokhi,  g_tok_hi);
    cudaGetSymbolAddress((void**)&toklo,  g_tok_lo);

    const int smem64 = G_SMEM(64);
    const int smem32 = G_SMEM(32);
    cudaFuncSetAttribute(bf16x3_gemm<EPI_NONE, 64>,
                         cudaFuncAttributeMaxDynamicSharedMemorySize, smem64);
    cudaFuncSetAttribute(bf16x3_gemm<EPI_QKV, 64>,
                         cudaFuncAttributeMaxDynamicSharedMemorySize, smem64);
    cudaFuncSetAttribute(bf16x3_gemm<EPI_GELU_SPLIT, 64>,
                         cudaFuncAttributeMaxDynamicSharedMemorySize, smem64);
    cudaFuncSetAttribute(bf16x3_gemm<EPI_RESID, 32>,
                         cudaFuncAttributeMaxDynamicSharedMemorySize, smem32);
    cudaFuncSetAttribute(attn_mma_kernel,
                         cudaFuncAttributeMaxDynamicSharedMemorySize, ATTN_SMEM_BYTES);

    // ---- prepass ----
    splitT_kernel<<<dim3(D_/32, D_/32, L_), 256>>>(
        wq, wqkvhi, wqkvlo, D_, D_, (size_t)D_*D_, (size_t)QKVN*D_, 0,     D_);
    splitT_kernel<<<dim3(D_/32, D_/32, L_), 256>>>(
        wk, wqkvhi, wqkvlo, D_, D_, (size_t)D_*D_, (size_t)QKVN*D_, D_,    D_);
    splitT_kernel<<<dim3(D_/32, D_/32, L_), 256>>>(
        wv, wqkvhi, wqkvlo, D_, D_, (size_t)D_*D_, (size_t)QKVN*D_, 2*D_,  D_);
    splitT_kernel<<<dim3(D_/32, D_/32, L_), 256>>>(
        wo, wohi, wolo, D_, D_, (size_t)D_*D_, (size_t)D_*D_, 0, D_);
    splitT_kernel<<<dim3(DF_/32, D_/32, L_), 256>>>(
        w1, w1hi, w1lo, D_, DF_, (size_t)D_*DF_, (size_t)DF_*D_, 0, D_);
    splitT_kernel<<<dim3(D_/32, DF_/32, L_), 256>>>(
        w2, w2hi, w2lo, DF_, D_, (size_t)DF_*D_, (size_t)D_*DF_, 0, DF_);
    split_kernel<<<2048, 256>>>(tok, tokhi, toklo, ((size_t)V_ * D_) / 4);
    bconcat_kernel<<<dim3(3, L_), 256>>>(bq, bk, bv, bqkv);

    embed_kernel<<<M_, 256>>>(ids, tok, pos, x);

    for (int l = 0; l < L_; l++) {
        ln_kernel<<<M_, 256>>>(x, ln1g + l * D_, ln1b + l * D_, hhi, hlo);

        bf16x3_gemm<EPI_QKV, 64><<<dim3(QKVN/64, M_/128), 256, smem64>>>(
            hhi, hlo,
            wqkvhi + (size_t)l * QKVN * D_, wqkvlo + (size_t)l * QKVN * D_,
            bqkv + l * QKVN, nullptr, nullptr,
            qhi, qlo, khi, klo, vhi, vlo,
            M_, QKVN, D_, QKVN);

        attn_mma_kernel<<<dim3(8, H_, B_), 128, ATTN_SMEM_BYTES>>>(
            qhi, qlo, khi, klo, vhi, vlo, atthi, attlo);

        bf16x3_gemm<EPI_RESID, 32><<<dim3(D_/32, M_/128), 256, smem32>>>(
            atthi, attlo,
            wohi + (size_t)l * D_ * D_, wolo + (size_t)l * D_ * D_,
            bo + l * D_, x, x, nullptr, nullptr, nullptr, nullptr, nullptr, nullptr,
            M_, D_, D_, D_);

        ln_kernel<<<M_, 256>>>(x, ln2g + l * D_, ln2b + l * D_, hhi, hlo);

        bf16x3_gemm<EPI_GELU_SPLIT, 64><<<dim3(DF_/64, M_/128), 256, smem64>>>(
            hhi, hlo,
            w1hi + (size_t)l * DF_ * D_, w1lo + (size_t)l * DF_ * D_,
            b1 + l * DF_, nullptr, nullptr, ffhi, fflo, nullptr, nullptr, nullptr, nullptr,
            M_, DF_, D_, DF_);

        bf16x3_gemm<EPI_RESID, 32><<<dim3(D_/32, M_/128), 256, smem32>>>(
            ffhi, fflo,
            w2hi + (size_t)l * D_ * DF_, w2lo + (size_t)l * D_ * DF_,
            b2 + l * D_, x, x, nullptr, nullptr, nullptr, nullptr, nullptr, nullptr,
            M_, D_, DF_, D_);
    }

    ln_kernel<<<M_, 256>>>(x, lnfg, lnfb, hhi, hlo);

    bf16x3_gemm<EPI_NONE, 64><<<dim3((V_ + 63) / 64, M_/128), 256, smem64>>>(
        hhi, hlo, tokhi, toklo,
        nullptr, nullptr, out, nullptr, nullptr, nullptr, nullptr, nullptr, nullptr,
        M_, V_, D_, V_);
}

// round 17
// speedup vs baseline: 1.0722x; 1.0197x over previous
#include <cuda_runtime.h>
#include <cuda_bf16.h>
#include <stdint.h>
#include <math.h>

// ---------------- problem constants ----------------
#define B_    2
#define S_    512
#define M_    1024
#define D_    768
#define H_    12
#define DK_   64
#define DF_   3072
#define L_    12
#define V_    50257
#define QKVN  (3 * D_)     // 2304
#define EPS_  1e-5f

// ---------------- scratch (device globals) ----------------
__device__ float          g_x[M_ * D_];
__device__ __nv_bfloat16  g_h_hi[M_ * D_],  g_h_lo[M_ * D_];
__device__ __nv_bfloat16  g_q_hi[M_ * D_],  g_q_lo[M_ * D_];
__device__ __nv_bfloat16  g_k_hi[M_ * D_],  g_k_lo[M_ * D_];
__device__ __nv_bfloat16  g_v_hi[M_ * D_],  g_v_lo[M_ * D_];
__device__ __nv_bfloat16  g_att_hi[M_ * D_], g_att_lo[M_ * D_];
__device__ __nv_bfloat16  g_ff_hi[M_ * DF_], g_ff_lo[M_ * DF_];
__device__ __nv_bfloat16  g_wqkv_hi[L_ * QKVN * D_], g_wqkv_lo[L_ * QKVN * D_];
__device__ __nv_bfloat16  g_wo_hi[L_ * D_ * D_],     g_wo_lo[L_ * D_ * D_];
__device__ __nv_bfloat16  g_w1_hi[L_ * DF_ * D_],    g_w1_lo[L_ * DF_ * D_];
__device__ __nv_bfloat16  g_w2_hi[L_ * D_ * DF_],    g_w2_lo[L_ * D_ * DF_];
__device__ __nv_bfloat16  g_tok_hi[(size_t)V_ * D_], g_tok_lo[(size_t)V_ * D_];
__device__ float          g_bqkv[L_ * QKVN];

// ---------------- small helpers ----------------
__device__ __forceinline__ void split_bf16(float x, __nv_bfloat16& hi, __nv_bfloat16& lo) {
    hi = __float2bfloat16(x);
    lo = __float2bfloat16(x - __bfloat162float(hi));
}

__device__ __forceinline__ uint32_t pack2(float lo, float hi) {
    __nv_bfloat162 t = __floats2bfloat162_rn(lo, hi);
    return *(uint32_t*)&t;
}

__device__ __forceinline__ uint32_t packbf(__nv_bfloat16 lo, __nv_bfloat16 hi) {
    return ((uint32_t)*(uint16_t*)&hi << 16) | (uint32_t)*(uint16_t*)&lo;
}

__device__ __forceinline__ void cp16(uint32_t saddr, const void* g) {
    asm volatile("cp.async.cg.shared.global [%0], [%1], 16;\n" :: "r"(saddr), "l"(g));
}
#define CP_COMMIT() asm volatile("cp.async.commit_group;\n" ::: "memory")

__device__ __forceinline__ void ldm4(uint32_t a[4], uint32_t saddr) {
    asm volatile("ldmatrix.sync.aligned.m8n8.x4.shared.b16 {%0,%1,%2,%3}, [%4];"
                 : "=r"(a[0]), "=r"(a[1]), "=r"(a[2]), "=r"(a[3]) : "r"(saddr));
}

__device__ __forceinline__ void ldm4t(uint32_t a[4], uint32_t saddr) {
    asm volatile("ldmatrix.sync.aligned.m8n8.x4.trans.shared.b16 {%0,%1,%2,%3}, [%4];"
                 : "=r"(a[0]), "=r"(a[1]), "=r"(a[2]), "=r"(a[3]) : "r"(saddr));
}

__device__ __forceinline__ void mma_bf16(float c[4], const uint32_t a[4], const uint32_t b[2]) {
    asm volatile("mma.sync.aligned.m16n8k16.row.col.f32.bf16.bf16.f32 "
                 "{%0,%1,%2,%3}, {%4,%5,%6,%7}, {%8,%9}, {%0,%1,%2,%3};"
                 : "+f"(c[0]), "+f"(c[1]), "+f"(c[2]), "+f"(c[3])
                 : "r"(a[0]), "r"(a[1]), "r"(a[2]), "r"(a[3]),
                   "r"(b[0]), "r"(b[1]));
}

// ---------------- prepass ----------------
__global__ void splitT_kernel(const float* __restrict__ src,
                              __nv_bfloat16* __restrict__ dhi,
                              __nv_bfloat16* __restrict__ dlo,
                              int K, int N,
                              size_t srcLayer, size_t dstLayer,
                              int dstRowOff, int dstLd) {
    __shared__ float t[32][33];
    int n0 = blockIdx.x * 32, k0 = blockIdx.y * 32, l = blockIdx.z;
    const float* s = src + (size_t)l * srcLayer;
    int c = threadIdx.x & 31, r8 = threadIdx.x >> 5;
    #pragma unroll
    for (int i = 0; i < 4; i++) {
        int r = r8 + i * 8;
        t[r][c] = s[(size_t)(k0 + r) * N + n0 + c];
    }
    __syncthreads();
    int c2 = threadIdx.x & 15, rr = threadIdx.x >> 4;
    #pragma unroll
    for (int i = 0; i < 2; i++) {
        int nloc = rr + i * 16;
        float x0 = t[2 * c2][nloc];
        float x1 = t[2 * c2 + 1][nloc];
        __nv_bfloat16 h0, l0, h1, l1;
        split_bf16(x0, h0, l0);
        split_bf16(x1, h1, l1);
        size_t o = (size_t)l * dstLayer + (size_t)(dstRowOff + n0 + nloc) * dstLd + k0 + 2 * c2;
        *(uint32_t*)&dhi[o] = packbf(h0, h1);
        *(uint32_t*)&dlo[o] = packbf(l0, l1);
    }
}

__global__ void split_kernel(const float* __restrict__ src,
                             __nv_bfloat16* __restrict__ dhi,
                             __nv_bfloat16* __restrict__ dlo, size_t n4) {
    const float4* s4 = (const float4*)src;
    uint2* dh = (uint2*)dhi;
    uint2* dl = (uint2*)dlo;
    size_t stride = (size_t)gridDim.x * blockDim.x;
    for (size_t i = (size_t)blockIdx.x * blockDim.x + threadIdx.x; i < n4; i += stride) {
        float4 v = s4[i];
        __nv_bfloat16 h0, l0, h1, l1, h2, l2, h3, l3;
        split_bf16(v.x, h0, l0);
        split_bf16(v.y, h1, l1);
        split_bf16(v.z, h2, l2);
        split_bf16(v.w, h3, l3);
        uint2 oh, ol;
        oh.x = packbf(h0, h1); oh.y = packbf(h2, h3);
        ol.x = packbf(l0, l1); ol.y = packbf(l2, l3);
        dh[i] = oh;
        dl[i] = ol;
    }
}

__global__ void bconcat_kernel(const float* __restrict__ bq,
                               const float* __restrict__ bk,
                               const float* __restrict__ bv,
                               float* __restrict__ o) {
    int l = blockIdx.y;
    int i = blockIdx.x * 256 + threadIdx.x;
    if (i < D_) {
        o[l * QKVN + i]           = bq[l * D_ + i];
        o[l * QKVN + D_ + i]      = bk[l * D_ + i];
        o[l * QKVN + 2 * D_ + i]  = bv[l * D_ + i];
    }
}

// ---------------- embedding ----------------
__global__ void embed_kernel(const int* __restrict__ ids,
                             const float* __restrict__ tok,
                             const float* __restrict__ pos,
                             float* __restrict__ x) {
    int r = blockIdx.x;
    int s = r % S_;
    int id = ids[r];
    const float* t = tok + (size_t)id * D_;
    const float* p = pos + (size_t)s  * D_;
    float* xr = x + (size_t)r * D_;
    for (int d = threadIdx.x; d < D_; d += blockDim.x)
        xr[d] = t[d] + p[d];
}

// ---------------- single-pass layernorm (warp-shuffle reduction) ----------------
__global__ void ln_kernel(const float* __restrict__ x,
                          const float* __restrict__ g,
                          const float* __restrict__ b,
                          __nv_bfloat16* __restrict__ yhi,
                          __nv_bfloat16* __restrict__ ylo) {
    __shared__ float w1s[8], w2s[8], stats[2];
    int r = blockIdx.x;
    int tid = threadIdx.x;
    int lane = tid & 31, warp = tid >> 5;
    const float* xr = x + (size_t)r * D_;

    float vals[3];
    float s1 = 0.f, s2 = 0.f;
    #pragma unroll
    for (int i = 0; i < 3; i++) {
        float v = xr[tid + i * 256];
        vals[i] = v;
        s1 += v;
        s2 += v * v;
    }
    #pragma unroll
    for (int o = 16; o > 0; o >>= 1) {
        s1 += __shfl_xor_sync(0xffffffff, s1, o);
        s2 += __shfl_xor_sync(0xffffffff, s2, o);
    }
    if (lane == 0) { w1s[warp] = s1; w2s[warp] = s2; }
    __syncthreads();
    if (warp == 0) {
        float a1 = (lane < 8) ? w1s[lane] : 0.f;
        float a2 = (lane < 8) ? w2s[lane] : 0.f;
        #pragma unroll
        for (int o = 4; o > 0; o >>= 1) {
            a1 += __shfl_xor_sync(0xffffffff, a1, o);
            a2 += __shfl_xor_sync(0xffffffff, a2, o);
        }
        if (lane == 0) {
            float mean = a1 * (1.0f / D_);
            float var  = a2 * (1.0f / D_) - mean * mean;
            stats[0] = mean;
            stats[1] = rsqrtf(var + EPS_);
        }
    }
    __syncthreads();
    float mean = stats[0], inv = stats[1];

    #pragma unroll
    for (int i = 0; i < 3; i++) {
        int d = tid + i * 256;
        float y = (vals[i] - mean) * inv * g[d] + b[d];
        __nv_bfloat16 hi, lo; split_bf16(y, hi, lo);
        yhi[(size_t)r * D_ + d] = hi;
        ylo[(size_t)r * D_ + d] = lo;
    }
}

enum { EPI_NONE = 0, EPI_RESID = 1, EPI_GELU_SPLIT = 2, EPI_QKV = 3 };

// ---------------- bf16x3 GEMM: 128xBN tile, 3-stage cp.async pipeline ----------------
#define G_STAGE(BN_) (16384 + 2 * (BN_) * 80)
#define G_SMEM(BN_)  (3 * G_STAGE(BN_))

template<int EPI, int BN_>
__global__ __launch_bounds__(256, 2)
void bf16x3_gemm(const __nv_bfloat16* __restrict__ Ahi,
                 const __nv_bfloat16* __restrict__ Alo,
                 const __nv_bfloat16* __restrict__ Bhi,
                 const __nv_bfloat16* __restrict__ Blo,
                 const float* __restrict__ bias,
                 const float* __restrict__ resid,
                 float* __restrict__ C,
                 __nv_bfloat16* __restrict__ Chi,
                 __nv_bfloat16* __restrict__ Clo,
                 __nv_bfloat16* __restrict__ Xhi,
                 __nv_bfloat16* __restrict__ Xlo,
                 __nv_bfloat16* __restrict__ Yhi,
                 __nv_bfloat16* __restrict__ Ylo,
                 int M, int N, int K, int ldc) {
    constexpr int NT = (BN_ == 64) ? 4 : 2;
    constexpr int STAGE = G_STAGE(BN_);
    extern __shared__ __align__(16) char smem_raw[];
    uint32_t sbase = (uint32_t)__cvta_generic_to_shared(smem_raw);

    int tid  = threadIdx.x;
    int lane = tid & 31;
    int warp = tid >> 5;
    int gid  = lane >> 2;
    int tig  = lane & 3;
    int wm   = (warp >> 1) * 32;
    int wn   = (warp & 1) * (BN_ / 2);
    int m0   = blockIdx.y * 128;
    int n0   = blockIdx.x * BN_;

    float acc[2][NT][4];
    #pragma unroll
    for (int i = 0; i < 2; i++)
        #pragma unroll
        for (int j = 0; j < NT; j++)
            #pragma unroll
            for (int e = 0; e < 4; e++) acc[i][j][e] = 0.f;

    auto loadStage = [&](int kt, int st) {
        uint32_t s0 = sbase + st * STAGE;
        int k0 = kt * 32;
        #pragma unroll
        for (int i = 0; i < 2; i++) {
            int cid = tid + i * 256;
            int r = cid >> 2, c = cid & 3;
            uint32_t soff = (uint32_t)((r * 4 + (c ^ ((r >> 1) & 3))) * 16);
            size_t go = (size_t)(m0 + r) * K + k0 + c * 8;
            cp16(s0 + soff,        Ahi + go);
            cp16(s0 + 8192 + soff, Alo + go);
        }
        for (int cid = tid; cid < BN_ * 4; cid += 256) {
            int r = cid >> 2, c = cid & 3;
            int rr = n0 + r; if (rr > N - 1) rr = N - 1;
            uint32_t soff = (uint32_t)(r * 80 + c * 16);
            size_t go = (size_t)rr * K + k0 + c * 8;
            cp16(s0 + 16384 + soff,            Bhi + go);
            cp16(s0 + 16384 + BN_ * 80 + soff, Blo + go);
        }
    };

    const int nIt = K / 32;
    loadStage(0, 0); CP_COMMIT();
    loadStage(1, 1); CP_COMMIT();

    int grp    = lane >> 3;
    int bRowLo = (lane & 7);
    int bKoff  = (grp & 1) ? 16 : 0;

    for (int it = 0; it < nIt; ++it) {
        if (it + 1 < nIt) asm volatile("cp.async.wait_group 1;\n" ::: "memory");
        else              asm volatile("cp.async.wait_group 0;\n" ::: "memory");
        __syncthreads();
        if (it + 2 < nIt) {
            loadStage(it + 2, (it + 2) % 3);
            CP_COMMIT();
        }

        int st = it % 3;
        uint32_t sAhiB = sbase + st * STAGE;
        uint32_t sAloB = sAhiB + 8192;
        uint32_t sBhiA = sAhiB + 16384;
        uint32_t sBloA = sBhiA + BN_ * 80;

        #pragma unroll
        for (int ks = 0; ks < 2; ks++) {
            uint32_t bh[NT][2], bl[NT][2];
            #pragma unroll
            for (int np = 0; np < NT / 2; np++) {
                int nt0 = np * 2, nt1 = np * 2 + 1;
                int nrow = wn + ((grp < 2) ? nt0 : nt1) * 8 + bRowLo;
                uint32_t off = (uint32_t)(nrow * 80 + ks * 32 + bKoff);
                uint32_t r4[4];
                ldm4(r4, sBhiA + off);
                bh[nt0][0] = r4[0]; bh[nt0][1] = r4[1];
                bh[nt1][0] = r4[2]; bh[nt1][1] = r4[3];
                ldm4(r4, sBloA + off);
                bl[nt0][0] = r4[0]; bl[nt0][1] = r4[1];
                bl[nt1][0] = r4[2]; bl[nt1][1] = r4[3];
            }
            #pragma unroll
            for (int mt = 0; mt < 2; mt++) {
                int r = wm + mt * 16 + (lane & 15);
                int c = ks * 2 + (lane >> 4);
                uint32_t soff = (uint32_t)((r * 4 + (c ^ ((r >> 1) & 3))) * 16);
                uint32_t ah[4], al[4];
                ldm4(ah, sAhiB + soff);
                ldm4(al, sAloB + soff);
                #pragma unroll
                for (int nt = 0; nt < NT; nt++) {
                    mma_bf16(acc[mt][nt], ah, bh[nt]);
                    mma_bf16(acc[mt][nt], ah, bl[nt]);
                    mma_bf16(acc[mt][nt], al, bh[nt]);
                }
            }
        }
    }

    // ---- epilogue ----
    int seg = 0;
    __nv_bfloat16 *DsHi = Chi, *DsLo = Clo;
    float qscale = 1.0f;
    if (EPI == EPI_QKV) {
        seg = n0 / D_;
        if (seg == 1) { DsHi = Xhi; DsLo = Xlo; }
        if (seg == 2) { DsHi = Yhi; DsLo = Ylo; }
        if (seg == 0) qscale = 0.125f;
    }

    #pragma unroll
    for (int mt = 0; mt < 2; mt++) {
        #pragma unroll
        for (int nt = 0; nt < NT; nt++) {
            #pragma unroll
            for (int half = 0; half < 2; half++) {
                int gm = m0 + wm + mt * 16 + gid + half * 8;
                int gn0 = n0 + wn + nt * 8 + tig * 2;
                if (EPI == EPI_QKV || EPI == EPI_GELU_SPLIT) {
                    float cv0 = acc[mt][nt][half * 2 + 0];
                    float cv1 = acc[mt][nt][half * 2 + 1];
                    if (bias) { cv0 += bias[gn0]; cv1 += bias[gn0 + 1]; }
                    if (EPI == EPI_QKV) { cv0 *= qscale; cv1 *= qscale; }
                    if (EPI == EPI_GELU_SPLIT) {
                        cv0 = 0.5f * cv0 * (1.0f + erff(cv0 * 0.70710678118654752f));
                        cv1 = 0.5f * cv1 * (1.0f + erff(cv1 * 0.70710678118654752f));
                    }
                    __nv_bfloat16 h0, l0, h1, l1;
                    split_bf16(cv0, h0, l0);
                    split_bf16(cv1, h1, l1);
                    size_t o = (EPI == EPI_QKV)
                             ? ((size_t)gm * D_ + (gn0 - seg * D_))
                             : ((size_t)gm * ldc + gn0);
                    __nv_bfloat16* dh = (EPI == EPI_QKV) ? DsHi : Chi;
                    __nv_bfloat16* dl = (EPI == EPI_QKV) ? DsLo : Clo;
                    *(uint32_t*)&dh[o] = packbf(h0, h1);
                    *(uint32_t*)&dl[o] = packbf(l0, l1);
                } else {
                    #pragma unroll
                    for (int e = 0; e < 2; e++) {
                        int gn = gn0 + e;
                        if (gn >= N) continue;
                        float cv = acc[mt][nt][half * 2 + e];
                        if (bias) cv += bias[gn];
                        size_t o = (size_t)gm * ldc + gn;
                        if (EPI == EPI_RESID) cv += resid[o];
                        C[o] = cv;
                    }
                }
            }
        }
    }
}

// ---------------- tensor-core flash attention (full ldmatrix) ----------------
// Q,K,V all [row][d] pitch 72 elems (144 B). Q/K frags via ldmatrix, V via .trans.
#define APITCH 72
#define ATTN_SMEM_BYTES (6 * 64 * APITCH * 2)

__global__ __launch_bounds__(128)
void attn_mma_kernel(const __nv_bfloat16* __restrict__ qhi,
                     const __nv_bfloat16* __restrict__ qlo,
                     const __nv_bfloat16* __restrict__ khi,
                     const __nv_bfloat16* __restrict__ klo,
                     const __nv_bfloat16* __restrict__ vhi,
                     const __nv_bfloat16* __restrict__ vlo,
                     __nv_bfloat16* __restrict__ ohi,
                     __nv_bfloat16* __restrict__ olo) {
    extern __shared__ __nv_bfloat16 sb[];
    __nv_bfloat16* sQh = sb;
    __nv_bfloat16* sQl = sb + 1 * 64 * APITCH;
    __nv_bfloat16* sKh = sb + 2 * 64 * APITCH;
    __nv_bfloat16* sKl = sb + 3 * 64 * APITCH;
    __nv_bfloat16* sVh = sb + 4 * 64 * APITCH;
    __nv_bfloat16* sVl = sb + 5 * 64 * APITCH;
    uint32_t sQhA = (uint32_t)__cvta_generic_to_shared(sQh);
    uint32_t sQlA = (uint32_t)__cvta_generic_to_shared(sQl);
    uint32_t sKhA = (uint32_t)__cvta_generic_to_shared(sKh);
    uint32_t sKlA = (uint32_t)__cvta_generic_to_shared(sKl);
    uint32_t sVhA = (uint32_t)__cvta_generic_to_shared(sVh);
    uint32_t sVlA = (uint32_t)__cvta_generic_to_shared(sVl);

    int qt = 7 - blockIdx.x;
    int h  = blockIdx.y;
    int b  = blockIdx.z;
    int tid  = threadIdx.x;
    int lane = tid & 31;
    int warp = tid >> 5;
    int gid  = lane >> 2;
    int tig  = lane & 3;
    int q0 = qt * 64;
    int rowbase = warp * 16;

    #pragma unroll
    for (int i = 0; i < 4; i++) {
        int idx = tid + i * 128;
        int r = idx >> 3, c = idx & 7;
        size_t go = (size_t)(b * S_ + q0 + r) * D_ + h * DK_ + c * 8;
        uint32_t soff = (uint32_t)(r * 144 + c * 16);
        cp16(sQhA + soff, qhi + go);
        cp16(sQlA + soff, qlo + go);
    }
    CP_COMMIT();

    float m0r = -1e30f, m1r = -1e30f;
    float l0r = 0.f,    l1r = 0.f;
    float oacc[8][4];
    #pragma unroll
    for (int i = 0; i < 8; i++)
        #pragma unroll
        for (int e = 0; e < 4; e++) oacc[i][e] = 0.f;

    // ldmatrix addressing
    int aRow   = rowbase + (lane & 15);          // Q a-frag row
    int aCsel  = (lane >> 4) * 8;                // Q a-frag col-half
    int grp    = lane >> 3;                      // K b-frag pairing
    int bRowLo = (lane & 7);
    int bKoff  = (grp & 1) ? 16 : 0;             // bytes
    int vrow   = (lane & 15);                    // V trans rows
    int vcolsel = (lane >> 4) * 8;

    for (int jt = 0; jt <= qt; jt++) {
        #pragma unroll
        for (int i = 0; i < 4; i++) {
            int idx = tid + i * 128;
            int r = idx >> 3, c = idx & 7;
            size_t go = (size_t)(b * S_ + jt * 64 + r) * D_ + h * DK_ + c * 8;
            uint32_t soff = (uint32_t)(r * 144 + c * 16);
            cp16(sKhA + soff, khi + go);
            cp16(sKlA + soff, klo + go);
            cp16(sVhA + soff, vhi + go);
            cp16(sVlA + soff, vlo + go);
        }
        CP_COMMIT();
        asm volatile("cp.async.wait_group 0;\n" ::: "memory");
        __syncthreads();

        float sc[8][4];
        #pragma unroll
        for (int i = 0; i < 8; i++)
            #pragma unroll
            for (int e = 0; e < 4; e++) sc[i][e] = 0.f;

        #pragma unroll
        for (int ks = 0; ks < 4; ks++) {
            // Q a-frags via ldmatrix.x4
            uint32_t aoff = (uint32_t)(aRow * 144 + (ks * 16 + aCsel) * 2);
            uint32_t ah[4], al[4];
            ldm4(ah, sQhA + aoff);
            ldm4(al, sQlA + aoff);
            // K b-frags via paired ldmatrix.x4 (2 nf per load)
            #pragma unroll
            for (int np = 0; np < 4; np++) {
                int nf0 = np * 2, nf1 = np * 2 + 1;
                int nrow = ((grp < 2) ? nf0 : nf1) * 8 + bRowLo;
                uint32_t off = (uint32_t)(nrow * 144 + ks * 32 + bKoff);
                uint32_t r4[4];
                uint32_t bh0[2], bh1[2], bl0[2], bl1[2];
                ldm4(r4, sKhA + off);
                bh0[0] = r4[0]; bh0[1] = r4[1];
                bh1[0] = r4[2]; bh1[1] = r4[3];
                ldm4(r4, sKlA + off);
                bl0[0] = r4[0]; bl0[1] = r4[1];
                bl1[0] = r4[2]; bl1[1] = r4[3];
                mma_bf16(sc[nf0], ah, bh0);
                mma_bf16(sc[nf0], ah, bl0);
                mma_bf16(sc[nf0], al, bh0);
                mma_bf16(sc[nf1], ah, bh1);
                mma_bf16(sc[nf1], ah, bl1);
                mma_bf16(sc[nf1], al, bh1);
            }
        }

        if (jt == qt) {
            int ql0 = rowbase + gid, ql1 = ql0 + 8;
            #pragma unroll
            for (int nf = 0; nf < 8; nf++) {
                int j0 = nf * 8 + 2 * tig;
                if (j0     > ql0) sc[nf][0] = -1e30f;
                if (j0 + 1 > ql0) sc[nf][1] = -1e30f;
                if (j0     > ql1) sc[nf][2] = -1e30f;
                if (j0 + 1 > ql1) sc[nf][3] = -1e30f;
            }
        }

        float mx0 = -1e30f, mx1 = -1e30f;
        #pragma unroll
        for (int nf = 0; nf < 8; nf++) {
            mx0 = fmaxf(mx0, fmaxf(sc[nf][0], sc[nf][1]));
            mx1 = fmaxf(mx1, fmaxf(sc[nf][2], sc[nf][3]));
        }
        mx0 = fmaxf(mx0, __shfl_xor_sync(0xffffffff, mx0, 1));
        mx0 = fmaxf(mx0, __shfl_xor_sync(0xffffffff, mx0, 2));
        mx1 = fmaxf(mx1, __shfl_xor_sync(0xffffffff, mx1, 1));
        mx1 = fmaxf(mx1, __shfl_xor_sync(0xffffffff, mx1, 2));

        float mn0 = fmaxf(m0r, mx0), mn1 = fmaxf(m1r, mx1);
        float al0 = __expf(m0r - mn0), al1 = __expf(m1r - mn1);
        m0r = mn0; m1r = mn1;

        float sum0 = 0.f, sum1 = 0.f;
        #pragma unroll
        for (int nf = 0; nf < 8; nf++) {
            sc[nf][0] = __expf(sc[nf][0] - mn0);
            sc[nf][1] = __expf(sc[nf][1] - mn0);
            sc[nf][2] = __expf(sc[nf][2] - mn1);
            sc[nf][3] = __expf(sc[nf][3] - mn1);
            sum0 += sc[nf][0] + sc[nf][1];
            sum1 += sc[nf][2] + sc[nf][3];
        }
        sum0 += __shfl_xor_sync(0xffffffff, sum0, 1);
        sum0 += __shfl_xor_sync(0xffffffff, sum0, 2);
        sum1 += __shfl_xor_sync(0xffffffff, sum1, 1);
        sum1 += __shfl_xor_sync(0xffffffff, sum1, 2);
        l0r = l0r * al0 + sum0;
        l1r = l1r * al1 + sum1;

        #pragma unroll
        for (int df = 0; df < 8; df++) {
            oacc[df][0] *= al0; oacc[df][1] *= al0;
            oacc[df][2] *= al1; oacc[df][3] *= al1;
        }

        #pragma unroll
        for (int ks = 0; ks < 4; ks++) {
            int f0 = 2 * ks, f1 = 2 * ks + 1;
            float h00 = __bfloat162float(__float2bfloat16(sc[f0][0]));
            float h01 = __bfloat162float(__float2bfloat16(sc[f0][1]));
            float h02 = __bfloat162float(__float2bfloat16(sc[f0][2]));
            float h03 = __bfloat162float(__float2bfloat16(sc[f0][3]));
            float h10 = __bfloat162float(__float2bfloat16(sc[f1][0]));
            float h11 = __bfloat162float(__float2bfloat16(sc[f1][1]));
            float h12 = __bfloat162float(__float2bfloat16(sc[f1][2]));
            float h13 = __bfloat162float(__float2bfloat16(sc[f1][3]));
            uint32_t ph[4], pl[4];
            ph[0] = pack2(h00, h01);
            ph[1] = pack2(h02, h03);
            ph[2] = pack2(h10, h11);
            ph[3] = pack2(h12, h13);
            pl[0] = pack2(sc[f0][0] - h00, sc[f0][1] - h01);
            pl[1] = pack2(sc[f0][2] - h02, sc[f0][3] - h03);
            pl[2] = pack2(sc[f1][0] - h10, sc[f1][1] - h11);
            pl[3] = pack2(sc[f1][2] - h12, sc[f1][3] - h13);

            uint32_t rowoff = (uint32_t)((ks * 16 + vrow) * 144);
            #pragma unroll
            for (int dp = 0; dp < 4; dp++) {
                uint32_t off = rowoff + (uint32_t)((dp * 16 + vcolsel) * 2);
                uint32_t r4h[4], r4l[4];
                ldm4t(r4h, sVhA + off);
                ldm4t(r4l, sVlA + off);
                uint32_t bh0[2] = { r4h[0], r4h[1] };
                uint32_t bh1[2] = { r4h[2], r4h[3] };
                uint32_t bl0[2] = { r4l[0], r4l[1] };
                uint32_t bl1[2] = { r4l[2], r4l[3] };
                mma_bf16(oacc[dp * 2],     ph, bh0);
                mma_bf16(oacc[dp * 2],     ph, bl0);
                mma_bf16(oacc[dp * 2],     pl, bh0);
                mma_bf16(oacc[dp * 2 + 1], ph, bh1);
                mma_bf16(oacc[dp * 2 + 1], ph, bl1);
                mma_bf16(oacc[dp * 2 + 1], pl, bh1);
            }
        }
        __syncthreads();
    }

    float inv0 = 1.0f / l0r, inv1 = 1.0f / l1r;
    int r0 = b * S_ + q0 + rowbase + gid;
    int r1 = r0 + 8;
    #pragma unroll
    for (int df = 0; df < 8; df++) {
        int d = h * DK_ + df * 8 + 2 * tig;
        float o0 = oacc[df][0] * inv0, o1 = oacc[df][1] * inv0;
        float o2 = oacc[df][2] * inv1, o3 = oacc[df][3] * inv1;
        __nv_bfloat16 hi0, lo0, hi1, lo1;
        split_bf16(o0, hi0, lo0); split_bf16(o1, hi1, lo1);
        *(uint32_t*)&ohi[(size_t)r0 * D_ + d] = packbf(hi0, hi1);
        *(uint32_t*)&olo[(size_t)r0 * D_ + d] = packbf(lo0, lo1);
        split_bf16(o2, hi0, lo0); split_bf16(o3, hi1, lo1);
        *(uint32_t*)&ohi[(size_t)r1 * D_ + d] = packbf(hi0, hi1);
        *(uint32_t*)&olo[(size_t)r1 * D_ + d] = packbf(lo0, lo1);
    }
}

// ---------------- host orchestration ----------------
extern "C" void kernel_launch(void* const* d_in, const int* in_sizes, int n_in,
                              void* d_out, int out_size) {
    const int*   ids   = (const int*)  d_in[0];
    const float* tok   = (const float*)d_in[1];
    const float* pos   = (const float*)d_in[2];
    const float* wq    = (const float*)d_in[3];
    const float* bq    = (const float*)d_in[4];
    const float* wk    = (const float*)d_in[5];
    const float* bk    = (const float*)d_in[6];
    const float* wv    = (const float*)d_in[7];
    const float* bv    = (const float*)d_in[8];
    const float* wo    = (const float*)d_in[9];
    const float* bo    = (const float*)d_in[10];
    const float* w1    = (const float*)d_in[11];
    const float* b1    = (const float*)d_in[12];
    const float* w2    = (const float*)d_in[13];
    const float* b2    = (const float*)d_in[14];
    const float* ln1g  = (const float*)d_in[15];
    const float* ln1b  = (const float*)d_in[16];
    const float* ln2g  = (const float*)d_in[17];
    const float* ln2b  = (const float*)d_in[18];
    const float* lnfg  = (const float*)d_in[19];
    const float* lnfb  = (const float*)d_in[20];
    float* out = (float*)d_out;

    float *x, *bqkv;
    __nv_bfloat16 *hhi, *hlo, *qhi, *qlo, *khi, *klo, *vhi, *vlo;
    __nv_bfloat16 *atthi, *attlo, *ffhi, *fflo;
    __nv_bfloat16 *wqkvhi, *wqkvlo, *wohi, *wolo, *w1hi, *w1lo, *w2hi, *w2lo, *tokhi, *toklo;
    cudaGetSymbolAddress((void**)&x,      g_x);
    cudaGetSymbolAddress((void**)&bqkv,   g_bqkv);
    cudaGetSymbolAddress((void**)&hhi,    g_h_hi);
    cudaGetSymbolAddress((void**)&hlo,    g_h_lo);
    cudaGetSymbolAddress((void**)&qhi,    g_q_hi);
    cudaGetSymbolAddress((void**)&qlo,    g_q_lo);
    cudaGetSymbolAddress((void**)&khi,    g_k_hi);
    cudaGetSymbolAddress((void**)&klo,    g_k_lo);
    cudaGetSymbolAddress((void**)&vhi,    g_v_hi);
    cudaGetSymbolAddress((void**)&vlo,    g_v_lo);
    cudaGetSymbolAddress((void**)&atthi,  g_att_hi);
    cudaGetSymbolAddress((void**)&attlo,  g_att_lo);
    cudaGetSymbolAddress((void**)&ffhi,   g_ff_hi);
    cudaGetSymbolAddress((void**)&fflo,   g_ff_lo);
    cudaGetSymbolAddress((void**)&wqkvhi, g_wqkv_hi);
    cudaGetSymbolAddress((void**)&wqkvlo, g_wqkv_lo);
    cudaGetSymbolAddress((void**)&wohi,   g_wo_hi);
    cudaGetSymbolAddress((void**)&wolo,   g_wo_lo);
    cudaGetSymbolAddress((void**)&w1hi,   g_w1_hi);
    cudaGetSymbolAddress((void**)&w1lo,   g_w1_lo);
    cudaGetSymbolAddress((void**)&w2hi,   g_w2_hi);
    cudaGetSymbolAddress((void**)&w2lo,   g_w2_lo);
    cudaGetSymbolAddress((void**)&tokhi,  g_tok_hi);
    cudaGetSymbolAddress((void**)&toklo,  g_tok_lo);

    const int smem64 = G_SMEM(64);
    const int smem32 = G_SMEM(32);
    cudaFuncSetAttribute(bf16x3_gemm<EPI_NONE, 64>,
                         cudaFuncAttributeMaxDynamicSharedMemorySize, smem64);
    cudaFuncSetAttribute(bf16x3_gemm<EPI_QKV, 64>,
                         cudaFuncAttributeMaxDynamicSharedMemorySize, smem64);
    cudaFuncSetAttribute(bf16x3_gemm<EPI_GELU_SPLIT, 64>,
                         cudaFuncAttributeMaxDynamicSharedMemorySize, smem64);
    cudaFuncSetAttribute(bf16x3_gemm<EPI_RESID, 32>,
                         cudaFuncAttributeMaxDynamicSharedMemorySize, smem32);
    cudaFuncSetAttribute(attn_mma_kernel,
                         cudaFuncAttributeMaxDynamicSharedMemorySize, ATTN_SMEM_BYTES);

    // ---- prepass ----
    splitT_kernel<<<dim3(D_/32, D_/32, L_), 256>>>(
        wq, wqkvhi, wqkvlo, D_, D_, (size_t)D_*D_, (size_t)QKVN*D_, 0,     D_);
    splitT_kernel<<<dim3(D_/32, D_/32, L_), 256>>>(
        wk, wqkvhi, wqkvlo, D_, D_, (size_t)D_*D_, (size_t)QKVN*D_, D_,    D_);
    splitT_kernel<<<dim3(D_/32, D_/32, L_), 256>>>(
        wv, wqkvhi, wqkvlo, D_, D_, (size_t)D_*D_, (size_t)QKVN*D_, 2*D_,  D_);
    splitT_kernel<<<dim3(D_/32, D_/32, L_), 256>>>(
        wo, wohi, wolo, D_, D_, (size_t)D_*D_, (size_t)D_*D_, 0, D_);
    splitT_kernel<<<dim3(DF_/32, D_/32, L_), 256>>>(
        w1, w1hi, w1lo, D_, DF_, (size_t)D_*DF_, (size_t)DF_*D_, 0, D_);
    splitT_kernel<<<dim3(D_/32, DF_/32, L_), 256>>>(
        w2, w2hi, w2lo, DF_, D_, (size_t)DF_*D_, (size_t)D_*DF_, 0, DF_);
    split_kernel<<<2048, 256>>>(tok, tokhi, toklo, ((size_t)V_ * D_) / 4);
    bconcat_kernel<<<dim3(3, L_), 256>>>(bq, bk, bv, bqkv);

    embed_kernel<<<M_, 256>>>(ids, tok, pos, x);

    for (int l = 0; l < L_; l++) {
        ln_kernel<<<M_, 256>>>(x, ln1g + l * D_, ln1b + l * D_, hhi, hlo);

        bf16x3_gemm<EPI_QKV, 64><<<dim3(QKVN/64, M_/128), 256, smem64>>>(
            hhi, hlo,
            wqkvhi + (size_t)l * QKVN * D_, wqkvlo + (size_t)l * QKVN * D_,
            bqkv + l * QKVN, nullptr, nullptr,
            qhi, qlo, khi, klo, vhi, vlo,
            M_, QKVN, D_, QKVN);

        attn_mma_kernel<<<dim3(8, H_, B_), 128, ATTN_SMEM_BYTES>>>(
            qhi, qlo, khi, klo, vhi, vlo, atthi, attlo);

        bf16x3_gemm<EPI_RESID, 32><<<dim3(D_/32, M_/128), 256, smem32>>>(
            atthi, attlo,
            wohi + (size_t)l * D_ * D_, wolo + (size_t)l * D_ * D_,
            bo + l * D_, x, x, nullptr, nullptr, nullptr, nullptr, nullptr, nullptr,
            M_, D_, D_, D_);

        ln_kernel<<<M_, 256>>>(x, ln2g + l * D_, ln2b + l * D_, hhi, hlo);

        bf16x3_gemm<EPI_GELU_SPLIT, 64><<<dim3(DF_/64, M_/128), 256, smem64>>>(
            hhi, hlo,
            w1hi + (size_t)l * DF_ * D_, w1lo + (size_t)l * DF_ * D_,
            b1 + l * DF_, nullptr, nullptr, ffhi, fflo, nullptr, nullptr, nullptr, nullptr,
            M_, DF_, D_, DF_);

        bf16x3_gemm<EPI_RESID, 32><<<dim3(D_/32, M_/128), 256, smem32>>>(
            ffhi, fflo,
            w2hi + (size_t)l * D_ * DF_, w2lo + (size_t)l * D_ * DF_,
            b2 + l * D_, x, x, nullptr, nullptr, nullptr, nullptr, nullptr, nullptr,
            M_, D_, DF_, D_);
    }

    ln_kernel<<<M_, 256>>>(x, lnfg, lnfb, hhi, hlo);

    bf16x3_gemm<EPI_NONE, 64><<<dim3((V_ + 63) / 64, M_/128), 256, smem64>>>(
        hhi, hlo, tokhi, toklo,
        nullptr, nullptr, out, nullptr, nullptr, nullptr, nullptr, nullptr, nullptr,
        M_, V_, D_, V_);
}